// round 2
// baseline (speedup 1.0000x reference)
#include <cuda_runtime.h>
#include <math.h>

#define M_TOT   8192      // B*N*S rows
#define KDIM    512       // H
#define NDIM    512
#define S_LEN   1024
#define NHEADS  8
#define DHEAD   64
#define GBN     64        // NHEADS * (B*N)

// -------- scratch (device globals; allocation-free rule) --------
__device__ float g_Q[NHEADS * 8 * S_LEN * DHEAD];   // [g][bn][s][d]
__device__ float g_K[NHEADS * 8 * S_LEN * DHEAD];
__device__ float g_V[NHEADS * 8 * S_LEN * DHEAD];
__device__ float g_Ycat[(size_t)M_TOT * NDIM];      // normalized, concat layout
__device__ float g_Gate[(size_t)M_TOT * NDIM];      // silu(X @ W_G)

// =================================================================
// Generic fp32 GEMM, 128x128 tile, BK=8, 256 threads, 8x8 per thread
// MODE 0: C = X @ W_head  -> headed layout g_Q/g_K/g_V (which selects)
// MODE 1: C = silu(X @ W_G) -> g_Gate (row-major)
// MODE 2: C = (g_Gate .* g_Ycat) @ W_O -> Cout (row-major, d_out)
// =================================================================
__device__ __forceinline__ float silu_f(float x) {
    return x / (1.0f + expf(-x));
}

template<int MODE>
__global__ void __launch_bounds__(256) gemm_k(const float* __restrict__ A,
                                              const float* __restrict__ B,
                                              float* __restrict__ Cout,
                                              int which)
{
    __shared__ float As[8][128];
    __shared__ float Bs[8][128];
    const int bm = blockIdx.y * 128;
    const int bn = blockIdx.x * 128;
    const int tid = threadIdx.x;
    const int tx = tid & 15;
    const int ty = tid >> 4;

    float acc[8][8];
#pragma unroll
    for (int i = 0; i < 8; i++)
#pragma unroll
        for (int j = 0; j < 8; j++) acc[i][j] = 0.0f;

    const int arow = tid >> 1, acol = (tid & 1) * 4;
    const int brow = tid >> 5, bcol = (tid & 31) * 4;

    for (int k0 = 0; k0 < KDIM; k0 += 8) {
        float4 av;
        if (MODE == 2) {
            size_t off = (size_t)(bm + arow) * KDIM + k0 + acol;
            float4 a1 = *(const float4*)&g_Gate[off];
            float4 a2 = *(const float4*)&g_Ycat[off];
            av = make_float4(a1.x * a2.x, a1.y * a2.y, a1.z * a2.z, a1.w * a2.w);
        } else {
            av = *(const float4*)&A[(size_t)(bm + arow) * KDIM + k0 + acol];
        }
        As[acol + 0][arow] = av.x;
        As[acol + 1][arow] = av.y;
        As[acol + 2][arow] = av.z;
        As[acol + 3][arow] = av.w;

        float4 bv;
        int cg = bn + bcol;
        if (MODE == 0) {
            // W is [heads][K][64]; column cg -> head cg>>6, dim cg&63
            bv = *(const float4*)&B[(size_t)(cg >> 6) * (KDIM * DHEAD)
                                    + (size_t)(k0 + brow) * DHEAD + (cg & 63)];
        } else {
            bv = *(const float4*)&B[(size_t)(k0 + brow) * NDIM + cg];
        }
        *(float4*)&Bs[brow][bcol] = bv;

        __syncthreads();
#pragma unroll
        for (int kk = 0; kk < 8; kk++) {
            float a[8], b[8];
            *(float4*)&a[0] = *(float4*)&As[kk][ty * 4];
            *(float4*)&a[4] = *(float4*)&As[kk][ty * 4 + 64];
            *(float4*)&b[0] = *(float4*)&Bs[kk][tx * 4];
            *(float4*)&b[4] = *(float4*)&Bs[kk][tx * 4 + 64];
#pragma unroll
            for (int i = 0; i < 8; i++)
#pragma unroll
                for (int j = 0; j < 8; j++)
                    acc[i][j] += a[i] * b[j];
        }
        __syncthreads();
    }

    float* Cq = nullptr;
    if (MODE == 0) Cq = (which == 0) ? g_Q : ((which == 1) ? g_K : g_V);

#pragma unroll
    for (int ih = 0; ih < 2; ih++) {
#pragma unroll
        for (int ii = 0; ii < 4; ii++) {
            int mg = bm + ih * 64 + ty * 4 + ii;
#pragma unroll
            for (int jh = 0; jh < 2; jh++) {
                int cg = bn + jh * 64 + tx * 4;
                float4 v;
                v.x = acc[ih * 4 + ii][jh * 4 + 0];
                v.y = acc[ih * 4 + ii][jh * 4 + 1];
                v.z = acc[ih * 4 + ii][jh * 4 + 2];
                v.w = acc[ih * 4 + ii][jh * 4 + 3];
                if (MODE == 0) {
                    *(float4*)&Cq[(size_t)(cg >> 6) * ((size_t)M_TOT * DHEAD)
                                  + (size_t)mg * DHEAD + (cg & 63)] = v;
                } else if (MODE == 1) {
                    v.x = silu_f(v.x); v.y = silu_f(v.y);
                    v.z = silu_f(v.z); v.w = silu_f(v.w);
                    *(float4*)&g_Gate[(size_t)mg * NDIM + cg] = v;
                } else {
                    *(float4*)&Cout[(size_t)mg * NDIM + cg] = v;
                }
            }
        }
    }
}

// =================================================================
// xpos rotary, in-place on g_Q (scaled) and g_K (inverse-scaled).
// One block per sequence position s; tables computed in double once.
// =================================================================
__global__ void __launch_bounds__(256) rotary_k()
{
    const int s = blockIdx.x;
    __shared__ float sn[32], cs[32], scl[32];
    if (threadIdx.x < 32) {
        int j = threadIdx.x;
        double invf = pow(10000.0, -(double)j / 32.0);
        double ang = (double)s * invf;
        sn[j] = (float)sin(ang);
        cs[j] = (float)cos(ang);
        double sv = ((double)(2 * j) + 0.4 * 64.0) / (1.4 * 64.0);
        scl[j] = (float)pow(sv, (double)s / 512.0);
    }
    __syncthreads();

    for (int t = threadIdx.x; t < GBN * 32; t += blockDim.x) {
        int row = t >> 5;     // g*8+bn
        int j = t & 31;
        size_t base = ((size_t)row * S_LEN + s) * DHEAD + 2 * j;
        float c = cs[j], si = sn[j], sc = scl[j], isc = 1.0f / scl[j];

        float q0 = g_Q[base], q1 = g_Q[base + 1];
        g_Q[base]     = (q0 * c - q1 * si) * sc;
        g_Q[base + 1] = (q1 * c + q0 * si) * sc;

        float k0 = g_K[base], k1 = g_K[base + 1];
        g_K[base]     = (k0 * c - k1 * si) * isc;
        g_K[base + 1] = (k1 * c + k0 * si) * isc;
    }
}

// =================================================================
// Causal retention (decayed QK^T then @V) + fused GroupNorm.
// Block: 64 query rows of one (g,bn). K/V tiles of 32. 256 threads.
// smem: QsT(16K) + KsT(8K) + Vs(8K) + ScT(8K) = 40KB.
// =================================================================
__global__ void __launch_bounds__(256) attn_k(const float* __restrict__ gnw,
                                              const float* __restrict__ gnb)
{
    const int qt  = blockIdx.x;     // 0..15
    const int gbn = blockIdx.y;     // 0..63
    const int g  = gbn >> 3;
    const int bn = gbn & 7;
    const int qbase = qt * 64;

    const float* Qp = g_Q + (size_t)gbn * S_LEN * DHEAD;
    const float* Kp = g_K + (size_t)gbn * S_LEN * DHEAD;
    const float* Vp = g_V + (size_t)gbn * S_LEN * DHEAD;

    __shared__ float QsT[64][64];   // [d][i]
    __shared__ float KsT[64][32];   // [d][j]
    __shared__ float Vs[32][64];    // [j][d]
    __shared__ float ScT[32][64];   // [j][i]

    const int tid = threadIdx.x;
    const int ti = tid & 15, t2 = tid >> 4;
    const int i0 = ti * 4;          // rows (both phases)
    const int j0 = t2 * 2;          // phase-1 score cols
    const int d0 = t2 * 4;          // phase-2 output cols

    // load Q tile, transposed, conflict-free (lane-major over rows)
    {
        int i = tid & 63, cg = (tid >> 6) * 4;
#pragma unroll
        for (int r = 0; r < 4; r++, cg += 16) {
            float4 v = *(const float4*)&Qp[(size_t)(qbase + i) * DHEAD + cg];
            QsT[cg + 0][i] = v.x; QsT[cg + 1][i] = v.y;
            QsT[cg + 2][i] = v.z; QsT[cg + 3][i] = v.w;
        }
    }

    // per-head decay: g_h = 1 - exp(linspace(ln 1/32, ln 1/512, 8))
    double tt = log(1.0 / 32.0) + (double)g * (log(1.0 / 512.0) - log(1.0 / 32.0)) / 7.0;
    float lng = (float)log(1.0 - exp(tt));

    float yacc[4][4];
#pragma unroll
    for (int a = 0; a < 4; a++)
#pragma unroll
        for (int b = 0; b < 4; b++) yacc[a][b] = 0.0f;

    const int nkt = 2 * qt + 2;
    for (int kt = 0; kt < nkt; kt++) {
        const int kbase = kt * 32;
        __syncthreads();   // prev-iter readers done before overwriting tiles

        // K tile transposed
        {
            int j = tid & 31, cg = (tid >> 5) * 4;
#pragma unroll
            for (int r = 0; r < 2; r++, cg += 32) {
                float4 v = *(const float4*)&Kp[(size_t)(kbase + j) * DHEAD + cg];
                KsT[cg + 0][j] = v.x; KsT[cg + 1][j] = v.y;
                KsT[cg + 2][j] = v.z; KsT[cg + 3][j] = v.w;
            }
        }
        // V tile natural, coalesced
        {
#pragma unroll
            for (int r = 0; r < 2; r++) {
                int idx = tid + r * 256;
                int j = idx >> 4, dd = (idx & 15) * 4;
                *(float4*)&Vs[j][dd] =
                    *(const float4*)&Vp[(size_t)(kbase + j) * DHEAD + dd];
            }
        }
        __syncthreads();

        // phase 1: 64x32 score tile, 4x2 per thread
        float sc[4][2];
#pragma unroll
        for (int a = 0; a < 4; a++) { sc[a][0] = 0.0f; sc[a][1] = 0.0f; }
#pragma unroll 16
        for (int d = 0; d < 64; d++) {
            float4 q = *(const float4*)&QsT[d][i0];
            float2 kv = *(const float2*)&KsT[d][j0];
            sc[0][0] += q.x * kv.x; sc[0][1] += q.x * kv.y;
            sc[1][0] += q.y * kv.x; sc[1][1] += q.y * kv.y;
            sc[2][0] += q.z * kv.x; sc[2][1] += q.z * kv.y;
            sc[3][0] += q.w * kv.x; sc[3][1] += q.w * kv.y;
        }
        // decay + causal mask + transposed write (register transpose, float4)
#pragma unroll
        for (int jj = 0; jj < 2; jj++) {
            int kj = kbase + j0 + jj;
            float4 col;
            float* cp = &col.x;
#pragma unroll
            for (int ii = 0; ii < 4; ii++) {
                int qi = qbase + i0 + ii;
                float f = (qi >= kj) ? __expf(lng * (float)(qi - kj)) : 0.0f;
                cp[ii] = sc[ii][jj] * f;
            }
            *(float4*)&ScT[j0 + jj][i0] = col;
        }
        __syncthreads();

        // phase 2: Y += Sc @ V, 4x4 per thread
#pragma unroll 8
        for (int j = 0; j < 32; j++) {
            float4 sv = *(const float4*)&ScT[j][i0];
            float4 vv = *(const float4*)&Vs[j][d0];
            yacc[0][0] += sv.x * vv.x; yacc[0][1] += sv.x * vv.y;
            yacc[0][2] += sv.x * vv.z; yacc[0][3] += sv.x * vv.w;
            yacc[1][0] += sv.y * vv.x; yacc[1][1] += sv.y * vv.y;
            yacc[1][2] += sv.y * vv.z; yacc[1][3] += sv.y * vv.w;
            yacc[2][0] += sv.z * vv.x; yacc[2][1] += sv.z * vv.y;
            yacc[2][2] += sv.z * vv.z; yacc[2][3] += sv.z * vv.w;
            yacc[3][0] += sv.w * vv.x; yacc[3][1] += sv.w * vv.y;
            yacc[3][2] += sv.w * vv.z; yacc[3][3] += sv.w * vv.w;
        }
    }

    // stage Y to smem (reuse QsT) and apply GroupNorm per row
    __syncthreads();
    float (*Ysm)[64] = QsT;
#pragma unroll
    for (int ii = 0; ii < 4; ii++)
        *(float4*)&Ysm[i0 + ii][d0] =
            make_float4(yacc[ii][0], yacc[ii][1], yacc[ii][2], yacc[ii][3]);
    __syncthreads();

    const int wid = tid >> 5, lane = tid & 31;
    float w0 = gnw[g * 64 + lane],      b0 = gnb[g * 64 + lane];
    float w1 = gnw[g * 64 + lane + 32], b1 = gnb[g * 64 + lane + 32];
#pragma unroll
    for (int rr = 0; rr < 8; rr++) {
        int r = wid * 8 + rr;
        float v0 = Ysm[r][lane], v1 = Ysm[r][lane + 32];
        float s = v0 + v1, sq = v0 * v0 + v1 * v1;
#pragma unroll
        for (int o = 16; o; o >>= 1) {
            s  += __shfl_xor_sync(0xffffffffu, s, o);
            sq += __shfl_xor_sync(0xffffffffu, sq, o);
        }
        float mean = s * (1.0f / 64.0f);
        float var = sq * (1.0f / 64.0f) - mean * mean;
        float rstd = rsqrtf(var + 1e-5f);
        size_t obase = ((size_t)bn * S_LEN + (qbase + r)) * NDIM + g * 64;
        g_Ycat[obase + lane]      = (v0 - mean) * rstd * w0 + b0;
        g_Ycat[obase + lane + 32] = (v1 - mean) * rstd * w1 + b1;
    }
}

// =================================================================
extern "C" void kernel_launch(void* const* d_in, const int* in_sizes, int n_in,
                              void* d_out, int out_size)
{
    const float* X   = (const float*)d_in[0];
    const float* WQ  = (const float*)d_in[1];
    const float* WK  = (const float*)d_in[2];
    const float* WV  = (const float*)d_in[3];
    const float* WG  = (const float*)d_in[4];
    const float* WO  = (const float*)d_in[5];
    const float* gnw = (const float*)d_in[6];
    const float* gnb = (const float*)d_in[7];
    float* out = (float*)d_out;

    dim3 gg(NDIM / 128, M_TOT / 128);   // (4, 64)

    gemm_k<0><<<gg, 256>>>(X, WQ, nullptr, 0);
    gemm_k<0><<<gg, 256>>>(X, WK, nullptr, 1);
    gemm_k<0><<<gg, 256>>>(X, WV, nullptr, 2);
    rotary_k<<<S_LEN, 256>>>();
    gemm_k<1><<<gg, 256>>>(X, WG, nullptr, 0);
    attn_k<<<dim3(16, GBN), 256>>>(gnw, gnb);
    gemm_k<2><<<gg, 256>>>(nullptr, WO, out, 0);
}

// round 3
// speedup vs baseline: 1.7971x; 1.7971x over previous
#include <cuda_runtime.h>
#include <math.h>

#define M_TOT   8192
#define KDIM    512
#define NDIM    512
#define S_LEN   1024
#define NHEADS  8
#define DHEAD   64
#define GBN     64

// -------- scratch (device globals) --------
__device__ float g_Q[NHEADS * 8 * S_LEN * DHEAD];
__device__ float g_K[NHEADS * 8 * S_LEN * DHEAD];
__device__ float g_V[NHEADS * 8 * S_LEN * DHEAD];
__device__ float g_Ycat[(size_t)M_TOT * NDIM];
__device__ float g_Gate[(size_t)M_TOT * NDIM];
__device__ float g_tsin[S_LEN * 32];
__device__ float g_tcos[S_LEN * 32];
__device__ float g_tscl[S_LEN * 32];

__device__ __forceinline__ unsigned f2tf(float x) {
    unsigned r;
    asm("cvt.rna.tf32.f32 %0, %1;" : "=r"(r) : "f"(x));
    return r;
}
__device__ __forceinline__ void mma_tf32(float* c, const unsigned* a, const unsigned* b) {
    asm volatile(
        "mma.sync.aligned.m16n8k8.row.col.f32.tf32.tf32.f32 "
        "{%0,%1,%2,%3},{%4,%5,%6,%7},{%8,%9},{%0,%1,%2,%3};"
        : "+f"(c[0]), "+f"(c[1]), "+f"(c[2]), "+f"(c[3])
        : "r"(a[0]), "r"(a[1]), "r"(a[2]), "r"(a[3]), "r"(b[0]), "r"(b[1]));
}
__device__ __forceinline__ float silu_f(float x) {
    return x / (1.0f + __expf(-x));
}

// =================================================================
// xpos tables: sin/cos/scale [s][j], computed in double, once per launch
// =================================================================
__global__ void tables_k() {
    int idx = blockIdx.x * 256 + threadIdx.x;   // 32768
    int s = idx >> 5, j = idx & 31;
    double invf = pow(10000.0, -(double)j / 32.0);
    double ang = (double)s * invf;
    g_tsin[idx] = (float)sin(ang);
    g_tcos[idx] = (float)cos(ang);
    double sv = (2.0 * j + 0.4 * 64.0) / (1.4 * 64.0);
    g_tscl[idx] = (float)pow(sv, (double)s / 512.0);
}

// =================================================================
// TF32 GEMM: 128x128 tile, BK=16, 128 threads (4 warps, 2x2, 64x64 each)
// MODE 0: C = X @ W_head -> headed g_Q/g_K/g_V, rotary fused (which 0=Q,1=K,2=V)
// MODE 1: C = silu(X @ W_G) -> g_Gate
// MODE 2: C = (g_Gate .* g_Ycat) @ W_O -> Cout
// =================================================================
template<int MODE>
__global__ void __launch_bounds__(128) gemm_tf32(const float* __restrict__ A,
                                                 const float* __restrict__ B,
                                                 float* __restrict__ Cout,
                                                 int which)
{
    __shared__ unsigned As[16][136];   // [k][m]
    __shared__ unsigned Bs[16][136];   // [k][n]
    const int bm = blockIdx.y * 128;
    const int bn = blockIdx.x * 128;
    const int tid = threadIdx.x;
    const int warp = tid >> 5, lane = tid & 31;
    const int grp = lane >> 2, tig = lane & 3;
    const int wm = (warp >> 1) * 64, wn = (warp & 1) * 64;

    float acc[4][8][4];
#pragma unroll
    for (int mt = 0; mt < 4; mt++)
#pragma unroll
        for (int nt = 0; nt < 8; nt++)
#pragma unroll
            for (int i = 0; i < 4; i++) acc[mt][nt][i] = 0.0f;

    const int bkr = tid >> 3, bnc = (tid & 7) * 16;

    for (int k0 = 0; k0 < KDIM; k0 += 16) {
        // ---- A tile: 128 rows x 16 k, one row per thread ----
        {
            size_t roff = (size_t)(bm + tid) * KDIM + k0;
#pragma unroll
            for (int c = 0; c < 4; c++) {
                float4 v;
                if (MODE == 2) {
                    float4 a1 = *(const float4*)&g_Gate[roff + 4 * c];
                    float4 a2 = *(const float4*)&g_Ycat[roff + 4 * c];
                    v = make_float4(a1.x * a2.x, a1.y * a2.y, a1.z * a2.z, a1.w * a2.w);
                } else {
                    v = *(const float4*)&A[roff + 4 * c];
                }
                As[4 * c + 0][tid] = f2tf(v.x);
                As[4 * c + 1][tid] = f2tf(v.y);
                As[4 * c + 2][tid] = f2tf(v.z);
                As[4 * c + 3][tid] = f2tf(v.w);
            }
        }
        // ---- B tile: 16 k x 128 n ----
        {
#pragma unroll
            for (int c = 0; c < 4; c++) {
                int cg = bn + bnc + 4 * c;
                float4 v;
                if (MODE == 0) {
                    v = *(const float4*)&B[(size_t)(cg >> 6) * (KDIM * DHEAD)
                                           + (size_t)(k0 + bkr) * DHEAD + (cg & 63)];
                } else {
                    v = *(const float4*)&B[(size_t)(k0 + bkr) * NDIM + cg];
                }
                uint4 u;
                u.x = f2tf(v.x); u.y = f2tf(v.y); u.z = f2tf(v.z); u.w = f2tf(v.w);
                *(uint4*)&Bs[bkr][bnc + 4 * c] = u;
            }
        }
        __syncthreads();

#pragma unroll
        for (int ks = 0; ks < 2; ks++) {
            int kk = ks * 8;
            unsigned aF[4][4];
#pragma unroll
            for (int mt = 0; mt < 4; mt++) {
                int m = wm + mt * 16 + grp;
                aF[mt][0] = As[kk + tig][m];
                aF[mt][1] = As[kk + tig][m + 8];
                aF[mt][2] = As[kk + tig + 4][m];
                aF[mt][3] = As[kk + tig + 4][m + 8];
            }
#pragma unroll
            for (int nt = 0; nt < 8; nt++) {
                unsigned bF[2];
                bF[0] = Bs[kk + tig][wn + nt * 8 + grp];
                bF[1] = Bs[kk + tig + 4][wn + nt * 8 + grp];
#pragma unroll
                for (int mt = 0; mt < 4; mt++)
                    mma_tf32(acc[mt][nt], aF[mt], bF);
            }
        }
        __syncthreads();
    }

    // ---- epilogue ----
    float* Cq = nullptr;
    if (MODE == 0) Cq = (which == 0) ? g_Q : ((which == 1) ? g_K : g_V);

#pragma unroll
    for (int mt = 0; mt < 4; mt++) {
        int row0 = bm + wm + mt * 16 + grp;
#pragma unroll
        for (int nt = 0; nt < 8; nt++) {
            int col = bn + wn + nt * 8 + tig * 2;
#pragma unroll
            for (int h = 0; h < 2; h++) {
                int row = row0 + h * 8;
                float c0 = acc[mt][nt][h * 2], c1 = acc[mt][nt][h * 2 + 1];
                if (MODE == 0) {
                    int gH = col >> 6, d = col & 63;
                    int s = row & 1023, bnIdx = row >> 10;
                    float o0 = c0, o1 = c1;
                    if (which != 2) {
                        int ti = (s << 5) + (d >> 1);
                        float sn = g_tsin[ti], cs = g_tcos[ti], sc = g_tscl[ti];
                        if (which == 1) sc = 1.0f / sc;
                        o0 = (c0 * cs - c1 * sn) * sc;
                        o1 = (c1 * cs + c0 * sn) * sc;
                    }
                    float* dst = Cq + (((size_t)(gH * 8 + bnIdx) * S_LEN + s) * DHEAD + d);
                    *(float2*)dst = make_float2(o0, o1);
                } else if (MODE == 1) {
                    *(float2*)&g_Gate[(size_t)row * NDIM + col] =
                        make_float2(silu_f(c0), silu_f(c1));
                } else {
                    *(float2*)&Cout[(size_t)row * NDIM + col] = make_float2(c0, c1);
                }
            }
        }
    }
}

// =================================================================
// Retention with TF32 mma: Q tile 128, K/V tiles 64, 128 threads.
// Warp w owns rows w*32..w*32+31 (2 m-tiles of 16). Fused GroupNorm.
// =================================================================
#define ATTN_SMEM (384 * 72 * 4 + 64 * 4)

__global__ void __launch_bounds__(128) attn_tf32(const float* __restrict__ gnw,
                                                 const float* __restrict__ gnb)
{
    extern __shared__ unsigned sm4[];
    unsigned (*Qs)[72]  = (unsigned(*)[72])sm4;               // 128 x 72
    unsigned (*KsT)[72] = (unsigned(*)[72])(sm4 + 128 * 72);  // 64 x 72  [d][key]
    unsigned (*Vs)[72]  = (unsigned(*)[72])(sm4 + 192 * 72);  // 64 x 72  [key][d]
    unsigned (*Ss)[72]  = (unsigned(*)[72])(sm4 + 256 * 72);  // 128 x 72 [row][key]
    float* Ce = (float*)(sm4 + 384 * 72);                     // 64

    const int qt  = 7 - blockIdx.x;      // big blocks first
    const int gbn = blockIdx.y;
    const int g  = gbn >> 3;
    const int bn = gbn & 7;
    const int qbase = qt * 128;

    const float* Qp = g_Q + (size_t)gbn * S_LEN * DHEAD;
    const float* Kp = g_K + (size_t)gbn * S_LEN * DHEAD;
    const float* Vp = g_V + (size_t)gbn * S_LEN * DHEAD;

    const int tid = threadIdx.x;
    const int warp = tid >> 5, lane = tid & 31;
    const int grp = lane >> 2, tig = lane & 3;

    double tt = log(1.0 / 32.0) + (double)g * (log(1.0 / 512.0) - log(1.0 / 32.0)) / 7.0;
    const float lng = (float)log(1.0 - exp(tt));

    // Q tile -> smem (tf32), one row per thread
    {
        size_t roff = (size_t)(qbase + tid) * DHEAD;
#pragma unroll
        for (int c = 0; c < 16; c++) {
            float4 v = *(const float4*)&Qp[roff + 4 * c];
            uint4 u;
            u.x = f2tf(v.x); u.y = f2tf(v.y); u.z = f2tf(v.z); u.w = f2tf(v.w);
            *(uint4*)&Qs[tid][4 * c] = u;
        }
    }
    if (tid < 64) Ce[tid] = __expf(lng * (float)(63 - tid));

    float eq[4];
#pragma unroll
    for (int i = 0; i < 4; i++)
        eq[i] = __expf(lng * (float)(warp * 32 + (i >> 1) * 16 + grp + (i & 1) * 8));

    float yacc[2][8][4];
#pragma unroll
    for (int mt = 0; mt < 2; mt++)
#pragma unroll
        for (int nt = 0; nt < 8; nt++)
#pragma unroll
            for (int i = 0; i < 4; i++) yacc[mt][nt][i] = 0.0f;

    const int nkt = 2 * qt + 2;
    for (int kt = 0; kt < nkt; kt++) {
        const int kbase = kt * 64;
        __syncthreads();

        // K tile transposed + V tile natural, tf32; 2 threads per key row
        {
            int key = tid >> 1, dh = (tid & 1) * 32;
            size_t koff = (size_t)(kbase + key) * DHEAD + dh;
#pragma unroll
            for (int c = 0; c < 8; c++) {
                float4 v = *(const float4*)&Kp[koff + 4 * c];
                int d0 = dh + 4 * c;
                KsT[d0 + 0][key] = f2tf(v.x);
                KsT[d0 + 1][key] = f2tf(v.y);
                KsT[d0 + 2][key] = f2tf(v.z);
                KsT[d0 + 3][key] = f2tf(v.w);
            }
            size_t voff = (size_t)(kbase + key) * DHEAD + dh;
#pragma unroll
            for (int c = 0; c < 8; c++) {
                float4 v = *(const float4*)&Vp[voff + 4 * c];
                uint4 u;
                u.x = f2tf(v.x); u.y = f2tf(v.y); u.z = f2tf(v.z); u.w = f2tf(v.w);
                *(uint4*)&Vs[key][dh + 4 * c] = u;
            }
        }
        __syncthreads();

        // ---- mma1: scores = Q @ K^T ----
        float sacc[2][8][4];
#pragma unroll
        for (int mt = 0; mt < 2; mt++)
#pragma unroll
            for (int nt = 0; nt < 8; nt++)
#pragma unroll
                for (int i = 0; i < 4; i++) sacc[mt][nt][i] = 0.0f;

#pragma unroll
        for (int ks = 0; ks < 8; ks++) {
            int kk = ks * 8;
            unsigned aF[2][4];
#pragma unroll
            for (int mt = 0; mt < 2; mt++) {
                int r = warp * 32 + mt * 16 + grp;
                aF[mt][0] = Qs[r][kk + tig];
                aF[mt][1] = Qs[r + 8][kk + tig];
                aF[mt][2] = Qs[r][kk + tig + 4];
                aF[mt][3] = Qs[r + 8][kk + tig + 4];
            }
#pragma unroll
            for (int nt = 0; nt < 8; nt++) {
                unsigned bF[2];
                bF[0] = KsT[kk + tig][nt * 8 + grp];
                bF[1] = KsT[kk + tig + 4][nt * 8 + grp];
                mma_tf32(sacc[0][nt], aF[0], bF);
                mma_tf32(sacc[1][nt], aF[1], bF);
            }
        }

        // ---- decay + causal mask, write S (tf32) ----
        const float tf = __expf(lng * (float)(qbase - kbase - 63));
#pragma unroll
        for (int mt = 0; mt < 2; mt++) {
            int rl0 = warp * 32 + mt * 16 + grp;
#pragma unroll
            for (int nt = 0; nt < 8; nt++) {
                int jl = nt * 8 + tig * 2;
                int kj = kbase + jl;
                float ce0 = Ce[jl], ce1 = Ce[jl + 1];
#pragma unroll
                for (int h = 0; h < 2; h++) {
                    int rl = rl0 + h * 8;
                    int qi = qbase + rl;
                    float rf = eq[mt * 2 + h] * tf;
                    float v0 = (qi >= kj)     ? sacc[mt][nt][h * 2]     * rf * ce0 : 0.0f;
                    float v1 = (qi >= kj + 1) ? sacc[mt][nt][h * 2 + 1] * rf * ce1 : 0.0f;
                    uint2 p;
                    p.x = f2tf(v0);
                    p.y = f2tf(v1);
                    *(uint2*)&Ss[rl][jl] = p;
                }
            }
        }
        __syncthreads();

        // ---- mma2: Y += S @ V ----
#pragma unroll
        for (int ks = 0; ks < 8; ks++) {
            int kk = ks * 8;
            unsigned aF[2][4];
#pragma unroll
            for (int mt = 0; mt < 2; mt++) {
                int r = warp * 32 + mt * 16 + grp;
                aF[mt][0] = Ss[r][kk + tig];
                aF[mt][1] = Ss[r + 8][kk + tig];
                aF[mt][2] = Ss[r][kk + tig + 4];
                aF[mt][3] = Ss[r + 8][kk + tig + 4];
            }
#pragma unroll
            for (int nt = 0; nt < 8; nt++) {
                unsigned bF[2];
                bF[0] = Vs[kk + tig][nt * 8 + grp];
                bF[1] = Vs[kk + tig + 4][nt * 8 + grp];
                mma_tf32(yacc[0][nt], aF[0], bF);
                mma_tf32(yacc[1][nt], aF[1], bF);
            }
        }
    }

    // ---- GroupNorm epilogue (row stats across tig subgroup) ----
#pragma unroll
    for (int mt = 0; mt < 2; mt++) {
#pragma unroll
        for (int h = 0; h < 2; h++) {
            int rl = warp * 32 + mt * 16 + grp + h * 8;
            int qi = qbase + rl;
            float s = 0.0f, sq = 0.0f;
#pragma unroll
            for (int nt = 0; nt < 8; nt++) {
                float v0 = yacc[mt][nt][h * 2], v1 = yacc[mt][nt][h * 2 + 1];
                s += v0 + v1;
                sq += v0 * v0 + v1 * v1;
            }
            s  += __shfl_xor_sync(0xffffffffu, s, 1);
            s  += __shfl_xor_sync(0xffffffffu, s, 2);
            sq += __shfl_xor_sync(0xffffffffu, sq, 1);
            sq += __shfl_xor_sync(0xffffffffu, sq, 2);
            float mean = s * (1.0f / 64.0f);
            float var = sq * (1.0f / 64.0f) - mean * mean;
            float rstd = rsqrtf(var + 1e-5f);
            size_t base = ((size_t)bn * S_LEN + qi) * NDIM + g * 64;
#pragma unroll
            for (int nt = 0; nt < 8; nt++) {
                int col = nt * 8 + tig * 2;
                float w0 = gnw[g * 64 + col], w1 = gnw[g * 64 + col + 1];
                float b0 = gnb[g * 64 + col], b1 = gnb[g * 64 + col + 1];
                float o0 = (yacc[mt][nt][h * 2] - mean) * rstd * w0 + b0;
                float o1 = (yacc[mt][nt][h * 2 + 1] - mean) * rstd * w1 + b1;
                *(float2*)&g_Ycat[base + col] = make_float2(o0, o1);
            }
        }
    }
}

// =================================================================
extern "C" void kernel_launch(void* const* d_in, const int* in_sizes, int n_in,
                              void* d_out, int out_size)
{
    const float* X   = (const float*)d_in[0];
    const float* WQ  = (const float*)d_in[1];
    const float* WK  = (const float*)d_in[2];
    const float* WV  = (const float*)d_in[3];
    const float* WG  = (const float*)d_in[4];
    const float* WO  = (const float*)d_in[5];
    const float* gnw = (const float*)d_in[6];
    const float* gnb = (const float*)d_in[7];
    float* out = (float*)d_out;

    cudaFuncSetAttribute(attn_tf32, cudaFuncAttributeMaxDynamicSharedMemorySize,
                         ATTN_SMEM);

    dim3 gg(NDIM / 128, M_TOT / 128);   // (4, 64)

    tables_k<<<128, 256>>>();
    gemm_tf32<0><<<gg, 128>>>(X, WQ, nullptr, 0);
    gemm_tf32<0><<<gg, 128>>>(X, WK, nullptr, 1);
    gemm_tf32<0><<<gg, 128>>>(X, WV, nullptr, 2);
    gemm_tf32<1><<<gg, 128>>>(X, WG, nullptr, 0);
    attn_tf32<<<dim3(8, GBN), 128, ATTN_SMEM>>>(gnw, gnb);
    gemm_tf32<2><<<gg, 128>>>(nullptr, WO, out, 0);
}

// round 4
// speedup vs baseline: 2.3690x; 1.3182x over previous
#include <cuda_runtime.h>
#include <math.h>

#define M_TOT   8192
#define KDIM    512
#define NDIM    512
#define S_LEN   1024
#define NHEADS  8
#define DHEAD   64
#define GBN     64
#define WSZ     262144     // 512*512 elements per weight

// -------- scratch (device globals, tf32 stored as unsigned) --------
__device__ unsigned g_Xt[(size_t)M_TOT * KDIM];
__device__ unsigned g_Wt[5 * WSZ];                 // WQ,WK,WV,WG,WO
__device__ unsigned g_Qt[GBN * S_LEN * DHEAD];
__device__ unsigned g_Kt[GBN * S_LEN * DHEAD];
__device__ unsigned g_Vt[GBN * S_LEN * DHEAD];
__device__ unsigned g_AG[(size_t)M_TOT * NDIM];    // tf32(gate * groupnorm(Y))
__device__ float    g_Gate[(size_t)M_TOT * NDIM];
__device__ float    g_tsin[S_LEN * 32];
__device__ float    g_tcos[S_LEN * 32];
__device__ float    g_tscl[S_LEN * 32];

__device__ __forceinline__ unsigned f2tf(float x) {
    unsigned r;
    asm("cvt.rna.tf32.f32 %0, %1;" : "=r"(r) : "f"(x));
    return r;
}
__device__ __forceinline__ void mma_tf32(float* c, const unsigned* a, const unsigned* b) {
    asm volatile(
        "mma.sync.aligned.m16n8k8.row.col.f32.tf32.tf32.f32 "
        "{%0,%1,%2,%3},{%4,%5,%6,%7},{%8,%9},{%0,%1,%2,%3};"
        : "+f"(c[0]), "+f"(c[1]), "+f"(c[2]), "+f"(c[3])
        : "r"(a[0]), "r"(a[1]), "r"(a[2]), "r"(a[3]), "r"(b[0]), "r"(b[1]));
}
__device__ __forceinline__ float silu_f(float x) {
    return x / (1.0f + __expf(-x));
}
__device__ __forceinline__ unsigned s2u(const void* p) {
    return (unsigned)__cvta_generic_to_shared(p);
}
#define CPA16(d, s) asm volatile("cp.async.ca.shared.global [%0], [%1], 16;" :: "r"(d), "l"(s))
#define CP_COMMIT() asm volatile("cp.async.commit_group;")
#define CP_WAIT(n)  asm volatile("cp.async.wait_group %0;" :: "n"(n))

// =================================================================
// prep: tf32-convert X and all weights; xpos tables in double
// =================================================================
__global__ void prep_k(const float* __restrict__ X, const float* __restrict__ WQ,
                       const float* __restrict__ WK, const float* __restrict__ WV,
                       const float* __restrict__ WG, const float* __restrict__ WO)
{
    int idx = blockIdx.x * 256 + threadIdx.x;
    if (idx < M_TOT * KDIM) { g_Xt[idx] = f2tf(X[idx]); return; }
    int off = idx - M_TOT * KDIM;
    if (off < 5 * WSZ) {
        int w = off >> 18, sub = off & (WSZ - 1);
        const float* p = (w == 0) ? WQ : (w == 1) ? WK : (w == 2) ? WV
                                  : (w == 3) ? WG : WO;
        g_Wt[off] = f2tf(p[sub]);
        return;
    }
    int t = off - 5 * WSZ;
    if (t < S_LEN * 32) {
        int s = t >> 5, j = t & 31;
        double invf = pow(10000.0, -(double)j / 32.0);
        double ang = (double)s * invf;
        g_tsin[t] = (float)sin(ang);
        g_tcos[t] = (float)cos(ang);
        double sv = (2.0 * j + 0.4 * 64.0) / (1.4 * 64.0);
        g_tscl[t] = (float)pow(sv, (double)s / 512.0);
    }
}

// =================================================================
// TF32 GEMM, 128x128 tile, BK=16, 256 thr (8 warps: 4m x 2n, 32x64 each),
// double-buffered cp.async.
// MODE 0: z=0..2 -> Q/K/V (rotary fused, tf32 out), z=3 -> silu gate (fp32)
// MODE 2: g_AG @ W_O -> fp32 out
// =================================================================
template<int MODE>
__global__ void __launch_bounds__(256) gemm2(float* __restrict__ Cout,
                                             const float* __restrict__ dummy)
{
    __shared__ unsigned As[2][128][20];   // [m][k], pad 4
    __shared__ unsigned Bs[2][16][136];   // [k][n], pad 8

    const int bz = (MODE == 0) ? blockIdx.z : 4;
    const unsigned* Ag = (MODE == 0) ? g_Xt : g_AG;
    const unsigned* Bg = g_Wt + (size_t)bz * WSZ;

    const int bm = blockIdx.y * 128;
    const int bn = blockIdx.x * 128;
    const int tid = threadIdx.x;
    const int warp = tid >> 5, lane = tid & 31;
    const int grp = lane >> 2, tig = lane & 3;
    const int wm = (warp & 3) * 32, wn = (warp >> 2) * 64;

    float acc[2][8][4];
#pragma unroll
    for (int mt = 0; mt < 2; mt++)
#pragma unroll
        for (int nt = 0; nt < 8; nt++)
#pragma unroll
            for (int i = 0; i < 4; i++) acc[mt][nt][i] = 0.0f;

    auto load_tiles = [&](int k0, int st) {
#pragma unroll
        for (int r = 0; r < 2; r++) {              // A: 512 x 16B chunks
            int c = tid + r * 256;
            int row = c >> 2, k4 = (c & 3) * 4;
            CPA16(s2u(&As[st][row][k4]),
                  &Ag[(size_t)(bm + row) * KDIM + k0 + k4]);
        }
#pragma unroll
        for (int r = 0; r < 2; r++) {              // B: 512 x 16B chunks
            int c = tid + r * 256;
            int k = c >> 5, n4 = (c & 31) * 4;
            int cg = bn + n4;
            size_t off = (bz < 3)
                ? ((size_t)(cg >> 6) * (KDIM * DHEAD) + (size_t)(k0 + k) * DHEAD + (cg & 63))
                : ((size_t)(k0 + k) * NDIM + cg);
            CPA16(s2u(&Bs[st][k][n4]), &Bg[off]);
        }
    };

    load_tiles(0, 0);
    CP_COMMIT();

    int st = 0;
    for (int it = 0; it < KDIM / 16; it++) {
        if (it + 1 < KDIM / 16) {
            load_tiles((it + 1) * 16, st ^ 1);
            CP_COMMIT();
            CP_WAIT(1);
        } else {
            CP_WAIT(0);
        }
        __syncthreads();

#pragma unroll
        for (int ks = 0; ks < 2; ks++) {
            int kk = ks * 8;
            unsigned aF[2][4];
#pragma unroll
            for (int mt = 0; mt < 2; mt++) {
                int m = wm + mt * 16 + grp;
                aF[mt][0] = As[st][m][kk + tig];
                aF[mt][1] = As[st][m + 8][kk + tig];
                aF[mt][2] = As[st][m][kk + tig + 4];
                aF[mt][3] = As[st][m + 8][kk + tig + 4];
            }
#pragma unroll
            for (int nt = 0; nt < 8; nt++) {
                unsigned bF[2];
                bF[0] = Bs[st][kk + tig][wn + nt * 8 + grp];
                bF[1] = Bs[st][kk + tig + 4][wn + nt * 8 + grp];
                mma_tf32(acc[0][nt], aF[0], bF);
                mma_tf32(acc[1][nt], aF[1], bF);
            }
        }
        __syncthreads();
        st ^= 1;
    }

    // ---- epilogue ----
    unsigned* Cq = (bz == 0) ? g_Qt : ((bz == 1) ? g_Kt : g_Vt);
#pragma unroll
    for (int mt = 0; mt < 2; mt++) {
        int row0 = bm + wm + mt * 16 + grp;
#pragma unroll
        for (int nt = 0; nt < 8; nt++) {
            int col = bn + wn + nt * 8 + tig * 2;
#pragma unroll
            for (int h = 0; h < 2; h++) {
                int row = row0 + h * 8;
                float c0 = acc[mt][nt][h * 2], c1 = acc[mt][nt][h * 2 + 1];
                if (MODE == 0) {
                    if (bz == 3) {
                        *(float2*)&g_Gate[(size_t)row * NDIM + col] =
                            make_float2(silu_f(c0), silu_f(c1));
                    } else {
                        int gH = col >> 6, d = col & 63;
                        int s = row & (S_LEN - 1), bnI = row >> 10;
                        float o0 = c0, o1 = c1;
                        if (bz < 2) {
                            int ti = (s << 5) + (d >> 1);
                            float sn = g_tsin[ti], cs = g_tcos[ti], sc = g_tscl[ti];
                            if (bz == 1) sc = 1.0f / sc;
                            o0 = (c0 * cs - c1 * sn) * sc;
                            o1 = (c1 * cs + c0 * sn) * sc;
                        }
                        unsigned* dst = Cq + (((size_t)(gH * 8 + bnI) * S_LEN + s) * DHEAD + d);
                        dst[0] = f2tf(o0);
                        dst[1] = f2tf(o1);
                    }
                } else {
                    *(float2*)&Cout[(size_t)row * NDIM + col] = make_float2(c0, c1);
                }
            }
        }
    }
}

// =================================================================
// Retention, 256 thr (8 warps x 16 rows), Q tile 128, K/V tiles 64.
// cp.async loads (pre-converted tf32). Fused GroupNorm + gate + tf32 out.
// =================================================================
#define ATTN_SMEM ((384 * 72 + 64) * 4)

__global__ void __launch_bounds__(256) attn_tf32(const float* __restrict__ gnw,
                                                 const float* __restrict__ gnb)
{
    extern __shared__ unsigned sm4[];
    unsigned (*Qs)[72] = (unsigned(*)[72])sm4;                // 128 x 72 [row][d]
    unsigned (*Ks)[72] = (unsigned(*)[72])(sm4 + 128 * 72);   // 64 x 72  [key][d]
    unsigned (*Vs)[72] = (unsigned(*)[72])(sm4 + 192 * 72);   // 64 x 72  [key][d]
    unsigned (*Ss)[72] = (unsigned(*)[72])(sm4 + 256 * 72);   // 128 x 72 [row][key]
    float* Ce = (float*)(sm4 + 384 * 72);                     // 64

    const int qt  = 7 - blockIdx.x;
    const int gbn = blockIdx.y;
    const int g  = gbn >> 3;
    const int bn = gbn & 7;
    const int qbase = qt * 128;

    const unsigned* Qp = g_Qt + (size_t)gbn * S_LEN * DHEAD;
    const unsigned* Kp = g_Kt + (size_t)gbn * S_LEN * DHEAD;
    const unsigned* Vp = g_Vt + (size_t)gbn * S_LEN * DHEAD;

    const int tid = threadIdx.x;
    const int warp = tid >> 5, lane = tid & 31;
    const int grp = lane >> 2, tig = lane & 3;

    double tt = log(1.0 / 32.0) + (double)g * (log(1.0 / 512.0) - log(1.0 / 32.0)) / 7.0;
    const float lng = (float)log(1.0 - exp(tt));

    auto load_kv = [&](int kbase) {
#pragma unroll
        for (int r = 0; r < 4; r++) {
            int c = tid + r * 256;
            int row = c >> 4, d4 = (c & 15) * 4;
            CPA16(s2u(&Ks[row][d4]), &Kp[(size_t)(kbase + row) * DHEAD + d4]);
        }
#pragma unroll
        for (int r = 0; r < 4; r++) {
            int c = tid + r * 256;
            int row = c >> 4, d4 = (c & 15) * 4;
            CPA16(s2u(&Vs[row][d4]), &Vp[(size_t)(kbase + row) * DHEAD + d4]);
        }
    };

    // Q tile + first K/V tile
#pragma unroll
    for (int r = 0; r < 8; r++) {
        int c = tid + r * 256;
        int row = c >> 4, d4 = (c & 15) * 4;
        CPA16(s2u(&Qs[row][d4]), &Qp[(size_t)(qbase + row) * DHEAD + d4]);
    }
    load_kv(0);
    CP_COMMIT();

    if (tid < 64) Ce[tid] = __expf(lng * (float)(63 - tid));
    float eq[2];
    eq[0] = __expf(lng * (float)(warp * 16 + grp));
    eq[1] = __expf(lng * (float)(warp * 16 + grp + 8));

    float yacc[8][4];
#pragma unroll
    for (int nt = 0; nt < 8; nt++)
#pragma unroll
        for (int i = 0; i < 4; i++) yacc[nt][i] = 0.0f;

    const int nkt = 2 * qt + 2;
    for (int kt = 0; kt < nkt; kt++) {
        const int kbase = kt * 64;
        CP_WAIT(0);
        __syncthreads();

        // ---- mma1: scores = Q @ K^T ----
        float sacc[8][4];
#pragma unroll
        for (int nt = 0; nt < 8; nt++)
#pragma unroll
            for (int i = 0; i < 4; i++) sacc[nt][i] = 0.0f;

#pragma unroll
        for (int ks = 0; ks < 8; ks++) {
            int kk = ks * 8;
            int r = warp * 16 + grp;
            unsigned aF[4];
            aF[0] = Qs[r][kk + tig];
            aF[1] = Qs[r + 8][kk + tig];
            aF[2] = Qs[r][kk + tig + 4];
            aF[3] = Qs[r + 8][kk + tig + 4];
#pragma unroll
            for (int nt = 0; nt < 8; nt++) {
                unsigned bF[2];
                bF[0] = Ks[nt * 8 + grp][kk + tig];
                bF[1] = Ks[nt * 8 + grp][kk + tig + 4];
                // note: B fragment wants B[k][n]; Ks natural is [n][k] = col-major ✓
                unsigned bG[2] = { bF[0], bF[1] };
                mma_tf32(sacc[nt], aF, bG);
            }
        }

        // ---- decay + causal mask -> S (tf32) ----
        const float tf = __expf(lng * (float)(qbase - kbase - 63));
        int rl0 = warp * 16 + grp;
#pragma unroll
        for (int nt = 0; nt < 8; nt++) {
            int jl = nt * 8 + tig * 2;
            int kj = kbase + jl;
            float ce0 = Ce[jl], ce1 = Ce[jl + 1];
#pragma unroll
            for (int h = 0; h < 2; h++) {
                int rl = rl0 + h * 8;
                int qi = qbase + rl;
                float rf = eq[h] * tf;
                float v0 = (qi >= kj)     ? sacc[nt][h * 2]     * rf * ce0 : 0.0f;
                float v1 = (qi >= kj + 1) ? sacc[nt][h * 2 + 1] * rf * ce1 : 0.0f;
                uint2 p;
                p.x = f2tf(v0);
                p.y = f2tf(v1);
                *(uint2*)&Ss[rl][jl] = p;
            }
        }
        __syncthreads();

        // ---- mma2: Y += S @ V ----
#pragma unroll
        for (int ks = 0; ks < 8; ks++) {
            int kk = ks * 8;
            int r = warp * 16 + grp;
            unsigned aF[4];
            aF[0] = Ss[r][kk + tig];
            aF[1] = Ss[r + 8][kk + tig];
            aF[2] = Ss[r][kk + tig + 4];
            aF[3] = Ss[r + 8][kk + tig + 4];
#pragma unroll
            for (int nt = 0; nt < 8; nt++) {
                unsigned bF[2];
                bF[0] = Vs[kk + tig][nt * 8 + grp];
                bF[1] = Vs[kk + tig + 4][nt * 8 + grp];
                mma_tf32(yacc[nt], aF, bF);
            }
        }
        __syncthreads();

        if (kt + 1 < nkt) {
            load_kv(kbase + 64);
            CP_COMMIT();
        }
    }

    // ---- GroupNorm + gate + tf32 store ----
#pragma unroll
    for (int h = 0; h < 2; h++) {
        int rl = warp * 16 + grp + h * 8;
        int qi = qbase + rl;
        float s = 0.0f, sq = 0.0f;
#pragma unroll
        for (int nt = 0; nt < 8; nt++) {
            float v0 = yacc[nt][h * 2], v1 = yacc[nt][h * 2 + 1];
            s += v0 + v1;
            sq += v0 * v0 + v1 * v1;
        }
        s  += __shfl_xor_sync(0xffffffffu, s, 1);
        s  += __shfl_xor_sync(0xffffffffu, s, 2);
        sq += __shfl_xor_sync(0xffffffffu, sq, 1);
        sq += __shfl_xor_sync(0xffffffffu, sq, 2);
        float mean = s * (1.0f / 64.0f);
        float var = sq * (1.0f / 64.0f) - mean * mean;
        float rstd = rsqrtf(var + 1e-5f);
        size_t base = ((size_t)bn * S_LEN + qi) * NDIM + g * 64;
#pragma unroll
        for (int nt = 0; nt < 8; nt++) {
            int col = nt * 8 + tig * 2;
            float w0 = gnw[g * 64 + col], w1 = gnw[g * 64 + col + 1];
            float b0 = gnb[g * 64 + col], b1 = gnb[g * 64 + col + 1];
            float2 gt = *(const float2*)&g_Gate[base + col];
            float o0 = ((yacc[nt][h * 2]     - mean) * rstd * w0 + b0) * gt.x;
            float o1 = ((yacc[nt][h * 2 + 1] - mean) * rstd * w1 + b1) * gt.y;
            uint2 p;
            p.x = f2tf(o0);
            p.y = f2tf(o1);
            *(uint2*)&g_AG[base + col] = p;
        }
    }
}

// =================================================================
extern "C" void kernel_launch(void* const* d_in, const int* in_sizes, int n_in,
                              void* d_out, int out_size)
{
    const float* X   = (const float*)d_in[0];
    const float* WQ  = (const float*)d_in[1];
    const float* WK  = (const float*)d_in[2];
    const float* WV  = (const float*)d_in[3];
    const float* WG  = (const float*)d_in[4];
    const float* WO  = (const float*)d_in[5];
    const float* gnw = (const float*)d_in[6];
    const float* gnb = (const float*)d_in[7];
    float* out = (float*)d_out;

    cudaFuncSetAttribute(attn_tf32, cudaFuncAttributeMaxDynamicSharedMemorySize,
                         ATTN_SMEM);

    int prep_elems = M_TOT * KDIM + 5 * WSZ + S_LEN * 32;
    prep_k<<<(prep_elems + 255) / 256, 256>>>(X, WQ, WK, WV, WG, WO);

    gemm2<0><<<dim3(NDIM / 128, M_TOT / 128, 4), 256>>>(nullptr, nullptr);
    attn_tf32<<<dim3(8, GBN), 256, ATTN_SMEM>>>(gnw, gnb);
    gemm2<2><<<dim3(NDIM / 128, M_TOT / 128, 1), 256>>>(out, nullptr);
}

// round 5
// speedup vs baseline: 2.5299x; 1.0679x over previous
#include <cuda_runtime.h>
#include <math.h>

#define M_TOT   8192
#define KDIM    512
#define NDIM    512
#define S_LEN   1024
#define NHEADS  8
#define DHEAD   64
#define GBN     64
#define WSZ     262144

// -------- scratch --------
__device__ unsigned g_Xt[(size_t)M_TOT * KDIM];
__device__ unsigned g_Wt[5 * WSZ];
__device__ unsigned g_Qt[GBN * S_LEN * DHEAD];
__device__ unsigned g_Kt[GBN * S_LEN * DHEAD];
__device__ unsigned g_Vt[GBN * S_LEN * DHEAD];
__device__ unsigned g_AG[(size_t)M_TOT * NDIM];
__device__ float    g_Gate[(size_t)M_TOT * NDIM];
__device__ float    g_tsin[S_LEN * 32];
__device__ float    g_tcos[S_LEN * 32];
__device__ float    g_tscl[S_LEN * 32];

__device__ __forceinline__ unsigned f2tf(float x) {
    unsigned r;
    asm("cvt.rna.tf32.f32 %0, %1;" : "=r"(r) : "f"(x));
    return r;
}
__device__ __forceinline__ void mma_tf32(float* c, const unsigned* a, const unsigned* b) {
    asm volatile(
        "mma.sync.aligned.m16n8k8.row.col.f32.tf32.tf32.f32 "
        "{%0,%1,%2,%3},{%4,%5,%6,%7},{%8,%9},{%0,%1,%2,%3};"
        : "+f"(c[0]), "+f"(c[1]), "+f"(c[2]), "+f"(c[3])
        : "r"(a[0]), "r"(a[1]), "r"(a[2]), "r"(a[3]), "r"(b[0]), "r"(b[1]));
}
__device__ __forceinline__ float silu_f(float x) {
    return x / (1.0f + __expf(-x));
}
__device__ __forceinline__ unsigned s2u(const void* p) {
    return (unsigned)__cvta_generic_to_shared(p);
}
#define CPA16(d, s) asm volatile("cp.async.ca.shared.global [%0], [%1], 16;" :: "r"(d), "l"(s))
#define CP_COMMIT() asm volatile("cp.async.commit_group;")
#define CP_WAIT(n)  asm volatile("cp.async.wait_group %0;" :: "n"(n))

// =================================================================
__global__ void prep_k(const float* __restrict__ X, const float* __restrict__ WQ,
                       const float* __restrict__ WK, const float* __restrict__ WV,
                       const float* __restrict__ WG, const float* __restrict__ WO)
{
    int idx = blockIdx.x * 256 + threadIdx.x;
    if (idx < M_TOT * KDIM) { g_Xt[idx] = f2tf(X[idx]); return; }
    int off = idx - M_TOT * KDIM;
    if (off < 5 * WSZ) {
        int w = off >> 18, sub = off & (WSZ - 1);
        const float* p = (w == 0) ? WQ : (w == 1) ? WK : (w == 2) ? WV
                                  : (w == 3) ? WG : WO;
        g_Wt[off] = f2tf(p[sub]);
        return;
    }
    int t = off - 5 * WSZ;
    if (t < S_LEN * 32) {
        int s = t >> 5, j = t & 31;
        double invf = pow(10000.0, -(double)j / 32.0);
        double ang = (double)s * invf;
        g_tsin[t] = (float)sin(ang);
        g_tcos[t] = (float)cos(ang);
        double sv = (2.0 * j + 0.4 * 64.0) / (1.4 * 64.0);
        g_tscl[t] = (float)pow(sv, (double)s / 512.0);
    }
}

// =================================================================
// TF32 GEMM, 128x128 tile, BK=16, 256 thr (8 warps 4m x 2n, 32x64),
// 3-stage cp.async, ONE sync per k-iter.
// =================================================================
#define NIT (KDIM / 16)
#define GEMM_SMEM ((3 * 128 * 20 + 3 * 16 * 136) * 4)

template<int MODE>
__global__ void __launch_bounds__(256) gemm2(float* __restrict__ Cout,
                                             const float* __restrict__ dummy)
{
    extern __shared__ unsigned gsm[];
    unsigned (*As)[20]  = (unsigned(*)[20])gsm;                     // [3*128][20]
    unsigned (*Bs)[136] = (unsigned(*)[136])(gsm + 3 * 128 * 20);   // [3*16][136]

    const int bz = (MODE == 0) ? blockIdx.z : 4;
    const unsigned* Ag = (MODE == 0) ? g_Xt : g_AG;
    const unsigned* Bg = g_Wt + (size_t)bz * WSZ;

    const int bm = blockIdx.y * 128;
    const int bn = blockIdx.x * 128;
    const int tid = threadIdx.x;
    const int warp = tid >> 5, lane = tid & 31;
    const int grp = lane >> 2, tig = lane & 3;
    const int wm = (warp & 3) * 32, wn = (warp >> 2) * 64;

    float acc[2][8][4];
#pragma unroll
    for (int mt = 0; mt < 2; mt++)
#pragma unroll
        for (int nt = 0; nt < 8; nt++)
#pragma unroll
            for (int i = 0; i < 4; i++) acc[mt][nt][i] = 0.0f;

    auto load_tiles = [&](int k0, int st) {
#pragma unroll
        for (int r = 0; r < 2; r++) {
            int c = tid + r * 256;
            int row = c >> 2, k4 = (c & 3) * 4;
            CPA16(s2u(&As[st * 128 + row][k4]),
                  &Ag[(size_t)(bm + row) * KDIM + k0 + k4]);
        }
#pragma unroll
        for (int r = 0; r < 2; r++) {
            int c = tid + r * 256;
            int k = c >> 5, n4 = (c & 31) * 4;
            int cg = bn + n4;
            size_t off = (bz < 3)
                ? ((size_t)(cg >> 6) * (KDIM * DHEAD) + (size_t)(k0 + k) * DHEAD + (cg & 63))
                : ((size_t)(k0 + k) * NDIM + cg);
            CPA16(s2u(&Bs[st * 16 + k][n4]), &Bg[off]);
        }
    };

    load_tiles(0, 0);  CP_COMMIT();
    load_tiles(16, 1); CP_COMMIT();

    for (int it = 0; it < NIT; it++) {
        const int st = it % 3;
        if (it + 1 < NIT) { CP_WAIT(1); } else { CP_WAIT(0); }
        __syncthreads();
        if (it + 2 < NIT) {
            load_tiles((it + 2) * 16, (it + 2) % 3);
            CP_COMMIT();
        }

#pragma unroll
        for (int ks = 0; ks < 2; ks++) {
            int kk = ks * 8;
            unsigned aF[2][4];
#pragma unroll
            for (int mt = 0; mt < 2; mt++) {
                int m = st * 128 + wm + mt * 16 + grp;
                aF[mt][0] = As[m][kk + tig];
                aF[mt][1] = As[m + 8][kk + tig];
                aF[mt][2] = As[m][kk + tig + 4];
                aF[mt][3] = As[m + 8][kk + tig + 4];
            }
#pragma unroll
            for (int nt = 0; nt < 8; nt++) {
                unsigned bF[2];
                bF[0] = Bs[st * 16 + kk + tig][wn + nt * 8 + grp];
                bF[1] = Bs[st * 16 + kk + tig + 4][wn + nt * 8 + grp];
                mma_tf32(acc[0][nt], aF[0], bF);
                mma_tf32(acc[1][nt], aF[1], bF);
            }
        }
    }

    unsigned* Cq = (bz == 0) ? g_Qt : ((bz == 1) ? g_Kt : g_Vt);
#pragma unroll
    for (int mt = 0; mt < 2; mt++) {
        int row0 = bm + wm + mt * 16 + grp;
#pragma unroll
        for (int nt = 0; nt < 8; nt++) {
            int col = bn + wn + nt * 8 + tig * 2;
#pragma unroll
            for (int h = 0; h < 2; h++) {
                int row = row0 + h * 8;
                float c0 = acc[mt][nt][h * 2], c1 = acc[mt][nt][h * 2 + 1];
                if (MODE == 0) {
                    if (bz == 3) {
                        *(float2*)&g_Gate[(size_t)row * NDIM + col] =
                            make_float2(silu_f(c0), silu_f(c1));
                    } else {
                        int gH = col >> 6, d = col & 63;
                        int s = row & (S_LEN - 1), bnI = row >> 10;
                        float o0 = c0, o1 = c1;
                        if (bz < 2) {
                            int ti = (s << 5) + (d >> 1);
                            float sn = g_tsin[ti], cs = g_tcos[ti], sc = g_tscl[ti];
                            if (bz == 1) sc = 1.0f / sc;
                            o0 = (c0 * cs - c1 * sn) * sc;
                            o1 = (c1 * cs + c0 * sn) * sc;
                        }
                        unsigned* dst = Cq + (((size_t)(gH * 8 + bnI) * S_LEN + s) * DHEAD + d);
                        dst[0] = f2tf(o0);
                        dst[1] = f2tf(o1);
                    }
                } else {
                    *(float2*)&Cout[(size_t)row * NDIM + col] = make_float2(c0, c1);
                }
            }
        }
    }
}

// =================================================================
// Retention: 256 thr (8 warps x 16 rows), Q tile 128, K/V tiles 64,
// 3-stage K/V cp.async pipeline, ONE sync per tile (S is warp-private
// by rows, so no mask->mma2 barrier). Fused GroupNorm + gate.
// Padded strides: Qs/Ks/Ss 76 (conflict-free for grp-varying lanes),
// Vs 72 (conflict-free for d-varying lanes).
// =================================================================
#define ATTN_SMEM ((128 * 76 + 3 * 64 * 76 + 3 * 64 * 72 + 128 * 76 + 64) * 4)

__global__ void __launch_bounds__(256) attn_tf32(const float* __restrict__ gnw,
                                                 const float* __restrict__ gnb)
{
    extern __shared__ unsigned sm4[];
    unsigned (*Qs)[76] = (unsigned(*)[76])sm4;                              // 128 x 76
    unsigned (*Ks)[76] = (unsigned(*)[76])(sm4 + 128 * 76);                 // 3*64 x 76
    unsigned (*Vs)[72] = (unsigned(*)[72])(sm4 + 128 * 76 + 192 * 76);      // 3*64 x 72
    unsigned (*Ss)[76] = (unsigned(*)[76])(sm4 + 128 * 76 + 192 * 76 + 192 * 72);
    float* Ce = (float*)(sm4 + 128 * 76 + 192 * 76 + 192 * 72 + 128 * 76);

    const int qt  = 7 - blockIdx.x;
    const int gbn = blockIdx.y;
    const int g  = gbn >> 3;
    const int bn = gbn & 7;
    const int qbase = qt * 128;

    const unsigned* Qp = g_Qt + (size_t)gbn * S_LEN * DHEAD;
    const unsigned* Kp = g_Kt + (size_t)gbn * S_LEN * DHEAD;
    const unsigned* Vp = g_Vt + (size_t)gbn * S_LEN * DHEAD;

    const int tid = threadIdx.x;
    const int warp = tid >> 5, lane = tid & 31;
    const int grp = lane >> 2, tig = lane & 3;

    double tt = log(1.0 / 32.0) + (double)g * (log(1.0 / 512.0) - log(1.0 / 32.0)) / 7.0;
    const float lng = (float)log(1.0 - exp(tt));

    auto load_kv = [&](int kt, int st) {
        int kbase = kt * 64;
#pragma unroll
        for (int r = 0; r < 4; r++) {
            int c = tid + r * 256;
            int row = c >> 4, d4 = (c & 15) * 4;
            CPA16(s2u(&Ks[st * 64 + row][d4]), &Kp[(size_t)(kbase + row) * DHEAD + d4]);
        }
#pragma unroll
        for (int r = 0; r < 4; r++) {
            int c = tid + r * 256;
            int row = c >> 4, d4 = (c & 15) * 4;
            CPA16(s2u(&Vs[st * 64 + row][d4]), &Vp[(size_t)(kbase + row) * DHEAD + d4]);
        }
    };

    const int nkt = 2 * qt + 2;

    // prologue: Q + KV0 in group0, KV1 in group1
#pragma unroll
    for (int r = 0; r < 8; r++) {
        int c = tid + r * 256;
        int row = c >> 4, d4 = (c & 15) * 4;
        CPA16(s2u(&Qs[row][d4]), &Qp[(size_t)(qbase + row) * DHEAD + d4]);
    }
    load_kv(0, 0); CP_COMMIT();
    load_kv(1, 1); CP_COMMIT();

    if (tid < 64) Ce[tid] = __expf(lng * (float)(63 - tid));
    float eq[2];
    eq[0] = __expf(lng * (float)(warp * 16 + grp));
    eq[1] = __expf(lng * (float)(warp * 16 + grp + 8));

    float yacc[8][4];
#pragma unroll
    for (int nt = 0; nt < 8; nt++)
#pragma unroll
        for (int i = 0; i < 4; i++) yacc[nt][i] = 0.0f;

    for (int kt = 0; kt < nkt; kt++) {
        const int st = kt % 3;
        const int kbase = kt * 64;
        if (kt + 1 < nkt) { CP_WAIT(1); } else { CP_WAIT(0); }
        __syncthreads();
        if (kt + 2 < nkt) { load_kv(kt + 2, (kt + 2) % 3); CP_COMMIT(); }

        // ---- mma1: scores = Q @ K^T ----
        float sacc[8][4];
#pragma unroll
        for (int nt = 0; nt < 8; nt++)
#pragma unroll
            for (int i = 0; i < 4; i++) sacc[nt][i] = 0.0f;

        const int r = warp * 16 + grp;
#pragma unroll
        for (int ks = 0; ks < 8; ks++) {
            int kk = ks * 8;
            unsigned aF[4];
            aF[0] = Qs[r][kk + tig];
            aF[1] = Qs[r + 8][kk + tig];
            aF[2] = Qs[r][kk + tig + 4];
            aF[3] = Qs[r + 8][kk + tig + 4];
#pragma unroll
            for (int nt = 0; nt < 8; nt++) {
                unsigned bF[2];
                bF[0] = Ks[st * 64 + nt * 8 + grp][kk + tig];
                bF[1] = Ks[st * 64 + nt * 8 + grp][kk + tig + 4];
                mma_tf32(sacc[nt], aF, bF);
            }
        }

        // ---- decay + causal mask -> S (tf32), warp-private rows ----
        const float tf = __expf(lng * (float)(qbase - kbase - 63));
#pragma unroll
        for (int nt = 0; nt < 8; nt++) {
            int jl = nt * 8 + tig * 2;
            int kj = kbase + jl;
            float ce0 = Ce[jl], ce1 = Ce[jl + 1];
#pragma unroll
            for (int h = 0; h < 2; h++) {
                int rl = r + h * 8;
                int qi = qbase + rl;
                float rf = eq[h] * tf;
                float v0 = (qi >= kj)     ? sacc[nt][h * 2]     * rf * ce0 : 0.0f;
                float v1 = (qi >= kj + 1) ? sacc[nt][h * 2 + 1] * rf * ce1 : 0.0f;
                uint2 p;
                p.x = f2tf(v0);
                p.y = f2tf(v1);
                *(uint2*)&Ss[rl][jl] = p;
            }
        }

        // ---- mma2: Y += S @ V (reads only own warp's rows of Ss) ----
#pragma unroll
        for (int ks = 0; ks < 8; ks++) {
            int kk = ks * 8;
            unsigned aF[4];
            aF[0] = Ss[r][kk + tig];
            aF[1] = Ss[r + 8][kk + tig];
            aF[2] = Ss[r][kk + tig + 4];
            aF[3] = Ss[r + 8][kk + tig + 4];
#pragma unroll
            for (int nt = 0; nt < 8; nt++) {
                unsigned bF[2];
                bF[0] = Vs[st * 64 + kk + tig][nt * 8 + grp];
                bF[1] = Vs[st * 64 + kk + tig + 4][nt * 8 + grp];
                mma_tf32(yacc[nt], aF, bF);
            }
        }
    }

    // ---- GroupNorm + gate + tf32 store ----
#pragma unroll
    for (int h = 0; h < 2; h++) {
        int rl = warp * 16 + grp + h * 8;
        int qi = qbase + rl;
        float s = 0.0f, sq = 0.0f;
#pragma unroll
        for (int nt = 0; nt < 8; nt++) {
            float v0 = yacc[nt][h * 2], v1 = yacc[nt][h * 2 + 1];
            s += v0 + v1;
            sq += v0 * v0 + v1 * v1;
        }
        s  += __shfl_xor_sync(0xffffffffu, s, 1);
        s  += __shfl_xor_sync(0xffffffffu, s, 2);
        sq += __shfl_xor_sync(0xffffffffu, sq, 1);
        sq += __shfl_xor_sync(0xffffffffu, sq, 2);
        float mean = s * (1.0f / 64.0f);
        float var = sq * (1.0f / 64.0f) - mean * mean;
        float rstd = rsqrtf(var + 1e-5f);
        size_t base = ((size_t)bn * S_LEN + qi) * NDIM + g * 64;
#pragma unroll
        for (int nt = 0; nt < 8; nt++) {
            int col = nt * 8 + tig * 2;
            float w0 = gnw[g * 64 + col], w1 = gnw[g * 64 + col + 1];
            float b0 = gnb[g * 64 + col], b1 = gnb[g * 64 + col + 1];
            float2 gt = *(const float2*)&g_Gate[base + col];
            float o0 = ((yacc[nt][h * 2]     - mean) * rstd * w0 + b0) * gt.x;
            float o1 = ((yacc[nt][h * 2 + 1] - mean) * rstd * w1 + b1) * gt.y;
            uint2 p;
            p.x = f2tf(o0);
            p.y = f2tf(o1);
            *(uint2*)&g_AG[base + col] = p;
        }
    }
}

// =================================================================
extern "C" void kernel_launch(void* const* d_in, const int* in_sizes, int n_in,
                              void* d_out, int out_size)
{
    const float* X   = (const float*)d_in[0];
    const float* WQ  = (const float*)d_in[1];
    const float* WK  = (const float*)d_in[2];
    const float* WV  = (const float*)d_in[3];
    const float* WG  = (const float*)d_in[4];
    const float* WO  = (const float*)d_in[5];
    const float* gnw = (const float*)d_in[6];
    const float* gnb = (const float*)d_in[7];
    float* out = (float*)d_out;

    cudaFuncSetAttribute(gemm2<0>, cudaFuncAttributeMaxDynamicSharedMemorySize, GEMM_SMEM);
    cudaFuncSetAttribute(gemm2<2>, cudaFuncAttributeMaxDynamicSharedMemorySize, GEMM_SMEM);
    cudaFuncSetAttribute(attn_tf32, cudaFuncAttributeMaxDynamicSharedMemorySize, ATTN_SMEM);

    int prep_elems = M_TOT * KDIM + 5 * WSZ + S_LEN * 32;
    prep_k<<<(prep_elems + 255) / 256, 256>>>(X, WQ, WK, WV, WG, WO);

    gemm2<0><<<dim3(NDIM / 128, M_TOT / 128, 4), 256, GEMM_SMEM>>>(nullptr, nullptr);
    attn_tf32<<<dim3(8, GBN), 256, ATTN_SMEM>>>(gnw, gnb);
    gemm2<2><<<dim3(NDIM / 128, M_TOT / 128, 1), 256, GEMM_SMEM>>>(out, nullptr);
}

// round 9
// speedup vs baseline: 3.7859x; 1.4964x over previous
#include <cuda_runtime.h>
#include <cuda_fp16.h>
#include <math.h>

#define M_TOT   8192
#define KDIM    512
#define NDIM    512
#define S_LEN   1024
#define NHEADS  8
#define DHEAD   64
#define GBN     64
#define WSZ     262144
#define KW      256        // k-words (half2) per row

// -------- scratch (packed half2 words) --------
__device__ unsigned g_Xh[(size_t)M_TOT * KW];
__device__ unsigned g_Wh[5 * WSZ / 2];              // transposed [w][n][k/2]
__device__ unsigned g_Qh[GBN * S_LEN * 32];         // [gbn][s][d/2]
__device__ unsigned g_Kh[GBN * S_LEN * 32];
__device__ unsigned g_Vh[GBN * DHEAD * 512];        // TRANSPOSED [gbn][d][s/2]
__device__ unsigned g_AGh[(size_t)M_TOT * 256];     // [row][n/2]
__device__ float    g_Gate[(size_t)M_TOT * NDIM];
__device__ float    g_tsin[S_LEN * 32];
__device__ float    g_tcos[S_LEN * 32];
__device__ float    g_tscl[S_LEN * 32];

__device__ __forceinline__ unsigned packh2(float a, float b) {
    __half2 h = __floats2half2_rn(a, b);
    return *reinterpret_cast<unsigned*>(&h);
}
__device__ __forceinline__ void mma_f16(float* c, const unsigned* a, const unsigned* b) {
    asm volatile(
        "mma.sync.aligned.m16n8k16.row.col.f32.f16.f16.f32 "
        "{%0,%1,%2,%3},{%4,%5,%6,%7},{%8,%9},{%0,%1,%2,%3};"
        : "+f"(c[0]), "+f"(c[1]), "+f"(c[2]), "+f"(c[3])
        : "r"(a[0]), "r"(a[1]), "r"(a[2]), "r"(a[3]), "r"(b[0]), "r"(b[1]));
}
__device__ __forceinline__ float silu_f(float x) {
    return x / (1.0f + __expf(-x));
}
__device__ __forceinline__ unsigned s2u(const void* p) {
    return (unsigned)__cvta_generic_to_shared(p);
}
#define CPA16(d, s) asm volatile("cp.async.ca.shared.global [%0], [%1], 16;" :: "r"(d), "l"(s))
#define CP_COMMIT() asm volatile("cp.async.commit_group;")
#define CP_WAIT(n)  asm volatile("cp.async.wait_group %0;" :: "n"(n))

// =================================================================
// prep: pack X, transposed weights to half2; xpos tables (double)
// =================================================================
__global__ void prep_k(const float* __restrict__ X, const float* __restrict__ WQ,
                       const float* __restrict__ WK, const float* __restrict__ WV,
                       const float* __restrict__ WG, const float* __restrict__ WO)
{
    int idx = blockIdx.x * 256 + threadIdx.x;
    const int XW = M_TOT * KW;
    if (idx < XW) {
        int row = idx >> 8, kw = idx & 255;
        const float* p = X + (size_t)row * KDIM + 2 * kw;
        g_Xh[idx] = packh2(p[0], p[1]);
        return;
    }
    int off = idx - XW;
    if (off < 5 * (WSZ / 2)) {
        int w = off >> 17, sub = off & (WSZ / 2 - 1);
        int n = sub >> 8, kw = sub & 255;
        int k0 = kw * 2;
        float v0, v1;
        if (w < 3) {
            const float* p = (w == 0) ? WQ : (w == 1) ? WK : WV;
            size_t hb = (size_t)(n >> 6) * (KDIM * DHEAD) + (n & 63);
            v0 = p[hb + (size_t)k0 * DHEAD];
            v1 = p[hb + (size_t)(k0 + 1) * DHEAD];
        } else {
            const float* p = (w == 3) ? WG : WO;
            v0 = p[(size_t)k0 * NDIM + n];
            v1 = p[(size_t)(k0 + 1) * NDIM + n];
        }
        g_Wh[off] = packh2(v0, v1);
        return;
    }
    int t = off - 5 * (WSZ / 2);
    if (t < S_LEN * 32) {
        int s = t >> 5, j = t & 31;
        double invf = pow(10000.0, -(double)j / 32.0);
        double ang = (double)s * invf;
        g_tsin[t] = (float)sin(ang);
        g_tcos[t] = (float)cos(ang);
        double sv = (2.0 * j + 0.4 * 64.0) / (1.4 * 64.0);
        g_tscl[t] = (float)pow(sv, (double)s / 512.0);
    }
}

// =================================================================
// fp16 GEMM: 128x128 tile, BK=32 halves (16 words -> 2 k16 MMA steps),
// 256 thr (8 warps 4m x 2n), 3-stage cp.async, one sync per k-iter.
// Stride 20 words (16B-aligned, conflict-free).
// MODE 0: bz 0..2 -> Q/K/V (rotary fused; V transposed), bz 3 -> gate.
// MODE 2: g_AGh @ WO^T -> fp32 out.
// =================================================================
#define NIT 16
#define GEMM_SMEM_H (2 * 3 * 128 * 20 * 4)

template<int MODE>
__global__ void __launch_bounds__(256) gemm_h(float* __restrict__ Cout)
{
    extern __shared__ unsigned gsm[];
    unsigned (*As)[20] = (unsigned(*)[20])gsm;                    // [3*128][20]
    unsigned (*Bs)[20] = (unsigned(*)[20])(gsm + 3 * 128 * 20);   // [3*128][20]

    const int bz = (MODE == 0) ? blockIdx.z : 4;
    const unsigned* Ag = (MODE == 0) ? g_Xh : g_AGh;
    const unsigned* Bg = g_Wh + (size_t)bz * (WSZ / 2);

    const int bm = blockIdx.y * 128;
    const int bn = blockIdx.x * 128;
    const int tid = threadIdx.x;
    const int warp = tid >> 5, lane = tid & 31;
    const int grp = lane >> 2, tig = lane & 3;
    const int wm = (warp & 3) * 32, wn = (warp >> 2) * 64;

    float acc[2][8][4];
#pragma unroll
    for (int mt = 0; mt < 2; mt++)
#pragma unroll
        for (int nt = 0; nt < 8; nt++)
#pragma unroll
            for (int i = 0; i < 4; i++) acc[mt][nt][i] = 0.0f;

    auto load_stage = [&](int s) {
        const int st = s % 3;
#pragma unroll
        for (int r = 0; r < 2; r++) {
            int c = tid + r * 256;
            int row = c >> 2, w4 = (c & 3) * 4;
            CPA16(s2u(&As[st * 128 + row][w4]),
                  &Ag[(size_t)(bm + row) * KW + s * 16 + w4]);
        }
#pragma unroll
        for (int r = 0; r < 2; r++) {
            int c = tid + r * 256;
            int row = c >> 2, w4 = (c & 3) * 4;
            CPA16(s2u(&Bs[st * 128 + row][w4]),
                  &Bg[(size_t)(bn + row) * KW + s * 16 + w4]);
        }
    };

    load_stage(0); CP_COMMIT();
    load_stage(1); CP_COMMIT();

    for (int it = 0; it < NIT; it++) {
        const int st = it % 3;
        if (it + 1 < NIT) { CP_WAIT(1); } else { CP_WAIT(0); }
        __syncthreads();
        if (it + 2 < NIT) { load_stage(it + 2); CP_COMMIT(); }

#pragma unroll
        for (int ks = 0; ks < 2; ks++) {            // 2 x k16 = 32 halves = BK
            int kw = ks * 8;
            unsigned aF[2][4];
#pragma unroll
            for (int mt = 0; mt < 2; mt++) {
                int m = st * 128 + wm + mt * 16 + grp;
                aF[mt][0] = As[m][kw + tig];
                aF[mt][1] = As[m + 8][kw + tig];
                aF[mt][2] = As[m][kw + tig + 4];
                aF[mt][3] = As[m + 8][kw + tig + 4];
            }
#pragma unroll
            for (int nt = 0; nt < 8; nt++) {
                int n = st * 128 + wn + nt * 8 + grp;
                unsigned bF[2];
                bF[0] = Bs[n][kw + tig];
                bF[1] = Bs[n][kw + tig + 4];
                mma_f16(acc[0][nt], aF[0], bF);
                mma_f16(acc[1][nt], aF[1], bF);
            }
        }
    }

    // ---- epilogue ----
#pragma unroll
    for (int mt = 0; mt < 2; mt++) {
        int row0 = bm + wm + mt * 16 + grp;
#pragma unroll
        for (int nt = 0; nt < 8; nt++) {
            int col = bn + wn + nt * 8 + tig * 2;   // even
#pragma unroll
            for (int h = 0; h < 2; h++) {
                int row = row0 + h * 8;
                float c0 = acc[mt][nt][h * 2], c1 = acc[mt][nt][h * 2 + 1];
                if (MODE == 0) {
                    if (bz == 3) {
                        *(float2*)&g_Gate[(size_t)row * NDIM + col] =
                            make_float2(silu_f(c0), silu_f(c1));
                    } else {
                        int gH = col >> 6, d = col & 63;
                        int s = row & (S_LEN - 1), bnI = row >> 10;
                        float o0 = c0, o1 = c1;
                        if (bz < 2) {
                            int ti = (s << 5) + (d >> 1);
                            float sn = g_tsin[ti], cs = g_tcos[ti], sc = g_tscl[ti];
                            if (bz == 1) sc = 1.0f / sc;
                            o0 = (c0 * cs - c1 * sn) * sc;
                            o1 = (c1 * cs + c0 * sn) * sc;
                        }
                        int gb = gH * 8 + bnI;
                        if (bz == 2) {
                            __half* vp = (__half*)g_Vh;
                            vp[((size_t)gb * 64 + d) * S_LEN + s]     = __float2half_rn(o0);
                            vp[((size_t)gb * 64 + d + 1) * S_LEN + s] = __float2half_rn(o1);
                        } else {
                            unsigned* dst = (bz == 0) ? g_Qh : g_Kh;
                            dst[((size_t)gb * S_LEN + s) * 32 + (d >> 1)] = packh2(o0, o1);
                        }
                    }
                } else {
                    *(float2*)&Cout[(size_t)row * NDIM + col] = make_float2(c0, c1);
                }
            }
        }
    }
}

// =================================================================
// Retention fp16: 256 thr (8 warps x 16 rows), Q tile 128, K/V tile 64,
// 3-stage K/V cp.async. V pre-transposed in gmem. Stride 36 words.
// K per tile = 64 halves = 32 words = 4 k16 steps. Fused GN + gate.
// =================================================================
#define ATTN_SMEM ((640 * 36 + 64) * 4)

__global__ void __launch_bounds__(256) attn_h(const float* __restrict__ gnw,
                                              const float* __restrict__ gnb)
{
    extern __shared__ unsigned sm4[];
    unsigned (*Qs)[36]  = (unsigned(*)[36])sm4;                       // 128 x [d/2]
    unsigned (*Ks)[36]  = (unsigned(*)[36])(sm4 + 128 * 36);          // 3*64 x [d/2]
    unsigned (*VsT)[36] = (unsigned(*)[36])(sm4 + 320 * 36);          // 3*64 (d) x [key/2]
    unsigned (*Ss)[36]  = (unsigned(*)[36])(sm4 + 512 * 36);          // 128 x [key/2]
    float* Ce = (float*)(sm4 + 640 * 36);

    const int qt  = 7 - blockIdx.x;
    const int gbn = blockIdx.y;
    const int g  = gbn >> 3;
    const int bn = gbn & 7;
    const int qbase = qt * 128;

    const unsigned* Qp = g_Qh + (size_t)gbn * S_LEN * 32;
    const unsigned* Kp = g_Kh + (size_t)gbn * S_LEN * 32;
    const unsigned* Vp = g_Vh + (size_t)gbn * DHEAD * 512;   // [d][s/2]

    const int tid = threadIdx.x;
    const int warp = tid >> 5, lane = tid & 31;
    const int grp = lane >> 2, tig = lane & 3;

    double tt = log(1.0 / 32.0) + (double)g * (log(1.0 / 512.0) - log(1.0 / 32.0)) / 7.0;
    const float lng = (float)log(1.0 - exp(tt));

    auto load_kv = [&](int kt, int st) {
        int kbase = kt * 64;
#pragma unroll
        for (int r = 0; r < 2; r++) {
            int c = tid + r * 256;
            int row = c >> 3, w4 = (c & 7) * 4;
            CPA16(s2u(&Ks[st * 64 + row][w4]), &Kp[(size_t)(kbase + row) * 32 + w4]);
        }
#pragma unroll
        for (int r = 0; r < 2; r++) {
            int c = tid + r * 256;
            int row = c >> 3, w4 = (c & 7) * 4;   // row = d
            CPA16(s2u(&VsT[st * 64 + row][w4]), &Vp[(size_t)row * 512 + (kbase >> 1) + w4]);
        }
    };

    const int nkt = 2 * qt + 2;

#pragma unroll
    for (int r = 0; r < 4; r++) {
        int c = tid + r * 256;
        int row = c >> 3, w4 = (c & 7) * 4;
        CPA16(s2u(&Qs[row][w4]), &Qp[(size_t)(qbase + row) * 32 + w4]);
    }
    load_kv(0, 0); CP_COMMIT();
    load_kv(1, 1); CP_COMMIT();

    if (tid < 64) Ce[tid] = __expf(lng * (float)(63 - tid));
    float eq[2];
    eq[0] = __expf(lng * (float)(warp * 16 + grp));
    eq[1] = __expf(lng * (float)(warp * 16 + grp + 8));

    float yacc[8][4];
#pragma unroll
    for (int nt = 0; nt < 8; nt++)
#pragma unroll
        for (int i = 0; i < 4; i++) yacc[nt][i] = 0.0f;

    const int r = warp * 16 + grp;

    for (int kt = 0; kt < nkt; kt++) {
        const int st = kt % 3;
        const int kbase = kt * 64;
        if (kt + 1 < nkt) { CP_WAIT(1); } else { CP_WAIT(0); }
        __syncthreads();
        if (kt + 2 < nkt) { load_kv(kt + 2, (kt + 2) % 3); CP_COMMIT(); }

        // ---- mma1: scores = Q @ K^T  (k = d = 64 halves, 4 steps) ----
        float sacc[8][4];
#pragma unroll
        for (int nt = 0; nt < 8; nt++)
#pragma unroll
            for (int i = 0; i < 4; i++) sacc[nt][i] = 0.0f;

#pragma unroll
        for (int ks = 0; ks < 4; ks++) {
            int kw = ks * 8;
            unsigned aF[4];
            aF[0] = Qs[r][kw + tig];
            aF[1] = Qs[r + 8][kw + tig];
            aF[2] = Qs[r][kw + tig + 4];
            aF[3] = Qs[r + 8][kw + tig + 4];
#pragma unroll
            for (int nt = 0; nt < 8; nt++) {
                unsigned bF[2];
                bF[0] = Ks[st * 64 + nt * 8 + grp][kw + tig];
                bF[1] = Ks[st * 64 + nt * 8 + grp][kw + tig + 4];
                mma_f16(sacc[nt], aF, bF);
            }
        }

        // ---- decay + causal mask -> S (half2), warp-private rows ----
        const float tf = __expf(lng * (float)(qbase - kbase - 63));
#pragma unroll
        for (int nt = 0; nt < 8; nt++) {
            int jl = nt * 8 + tig * 2;
            int kj = kbase + jl;
            float ce0 = Ce[jl], ce1 = Ce[jl + 1];
#pragma unroll
            for (int h = 0; h < 2; h++) {
                int rl = r + h * 8;
                int qi = qbase + rl;
                float rf = eq[h] * tf;
                float v0 = (qi >= kj)     ? sacc[nt][h * 2]     * rf * ce0 : 0.0f;
                float v1 = (qi >= kj + 1) ? sacc[nt][h * 2 + 1] * rf * ce1 : 0.0f;
                Ss[rl][nt * 4 + tig] = packh2(v0, v1);
            }
        }
        __syncwarp();

        // ---- mma2: Y += S @ V^T-tile  (k = key = 64 halves, 4 steps) ----
#pragma unroll
        for (int ks = 0; ks < 4; ks++) {
            int kw = ks * 8;
            unsigned aF[4];
            aF[0] = Ss[r][kw + tig];
            aF[1] = Ss[r + 8][kw + tig];
            aF[2] = Ss[r][kw + tig + 4];
            aF[3] = Ss[r + 8][kw + tig + 4];
#pragma unroll
            for (int nt = 0; nt < 8; nt++) {
                unsigned bF[2];
                bF[0] = VsT[st * 64 + nt * 8 + grp][kw + tig];
                bF[1] = VsT[st * 64 + nt * 8 + grp][kw + tig + 4];
                mma_f16(yacc[nt], aF, bF);
            }
        }
    }

    // ---- GroupNorm + gate + half2 store ----
#pragma unroll
    for (int h = 0; h < 2; h++) {
        int rl = warp * 16 + grp + h * 8;
        int qi = qbase + rl;
        float s = 0.0f, sq = 0.0f;
#pragma unroll
        for (int nt = 0; nt < 8; nt++) {
            float v0 = yacc[nt][h * 2], v1 = yacc[nt][h * 2 + 1];
            s += v0 + v1;
            sq += v0 * v0 + v1 * v1;
        }
        s  += __shfl_xor_sync(0xffffffffu, s, 1);
        s  += __shfl_xor_sync(0xffffffffu, s, 2);
        sq += __shfl_xor_sync(0xffffffffu, sq, 1);
        sq += __shfl_xor_sync(0xffffffffu, sq, 2);
        float mean = s * (1.0f / 64.0f);
        float var = sq * (1.0f / 64.0f) - mean * mean;
        float rstd = rsqrtf(var + 1e-5f);
        size_t fbase = ((size_t)bn * S_LEN + qi) * NDIM + g * 64;
#pragma unroll
        for (int nt = 0; nt < 8; nt++) {
            int col = nt * 8 + tig * 2;
            float w0 = gnw[g * 64 + col], w1 = gnw[g * 64 + col + 1];
            float b0 = gnb[g * 64 + col], b1 = gnb[g * 64 + col + 1];
            float2 gt = *(const float2*)&g_Gate[fbase + col];
            float o0 = ((yacc[nt][h * 2]     - mean) * rstd * w0 + b0) * gt.x;
            float o1 = ((yacc[nt][h * 2 + 1] - mean) * rstd * w1 + b1) * gt.y;
            g_AGh[(fbase + col) >> 1] = packh2(o0, o1);
        }
    }
}

// =================================================================
extern "C" void kernel_launch(void* const* d_in, const int* in_sizes, int n_in,
                              void* d_out, int out_size)
{
    const float* X   = (const float*)d_in[0];
    const float* WQ  = (const float*)d_in[1];
    const float* WK  = (const float*)d_in[2];
    const float* WV  = (const float*)d_in[3];
    const float* WG  = (const float*)d_in[4];
    const float* WO  = (const float*)d_in[5];
    const float* gnw = (const float*)d_in[6];
    const float* gnb = (const float*)d_in[7];
    float* out = (float*)d_out;

    cudaFuncSetAttribute(gemm_h<0>, cudaFuncAttributeMaxDynamicSharedMemorySize, GEMM_SMEM_H);
    cudaFuncSetAttribute(gemm_h<2>, cudaFuncAttributeMaxDynamicSharedMemorySize, GEMM_SMEM_H);
    cudaFuncSetAttribute(attn_h, cudaFuncAttributeMaxDynamicSharedMemorySize, ATTN_SMEM);

    int prep_elems = M_TOT * KW + 5 * (WSZ / 2) + S_LEN * 32;
    prep_k<<<(prep_elems + 255) / 256, 256>>>(X, WQ, WK, WV, WG, WO);

    gemm_h<0><<<dim3(NDIM / 128, M_TOT / 128, 4), 256, GEMM_SMEM_H>>>(nullptr);
    attn_h<<<dim3(8, GBN), 256, ATTN_SMEM>>>(gnw, gnb);
    gemm_h<2><<<dim3(NDIM / 128, M_TOT / 128, 1), 256, GEMM_SMEM_H>>>(out);
}

// round 11
// speedup vs baseline: 4.1029x; 1.0837x over previous
#include <cuda_runtime.h>
#include <cuda_fp16.h>
#include <math.h>

#define M_TOT   8192
#define KDIM    512
#define NDIM    512
#define S_LEN   1024
#define NHEADS  8
#define DHEAD   64
#define GBN     64
#define WSZ     262144
#define KW      256        // k-words (half2) per row

// -------- scratch (packed half2 words) --------
__device__ unsigned g_Xh[(size_t)M_TOT * KW];
__device__ unsigned g_Wh[5 * WSZ / 2];              // transposed [w][n][k/2]
__device__ unsigned g_Qh[GBN * S_LEN * 32];         // [gbn][s][d/2]
__device__ unsigned g_Kh[GBN * S_LEN * 32];
__device__ unsigned g_Vh[GBN * DHEAD * 512];        // TRANSPOSED [gbn][d][s/2]
__device__ unsigned g_AGh[(size_t)M_TOT * 256];     // [row][n/2]
__device__ float    g_Gate[(size_t)M_TOT * NDIM];
__device__ float    g_tsin[S_LEN * 32];
__device__ float    g_tcos[S_LEN * 32];
__device__ float    g_tscl[S_LEN * 32];

__device__ __forceinline__ unsigned packh2(float a, float b) {
    __half2 h = __floats2half2_rn(a, b);
    return *reinterpret_cast<unsigned*>(&h);
}
__device__ __forceinline__ void mma_f16(float* c, const unsigned* a, const unsigned* b) {
    asm volatile(
        "mma.sync.aligned.m16n8k16.row.col.f32.f16.f16.f32 "
        "{%0,%1,%2,%3},{%4,%5,%6,%7},{%8,%9},{%0,%1,%2,%3};"
        : "+f"(c[0]), "+f"(c[1]), "+f"(c[2]), "+f"(c[3])
        : "r"(a[0]), "r"(a[1]), "r"(a[2]), "r"(a[3]), "r"(b[0]), "r"(b[1]));
}
__device__ __forceinline__ void ldsm4(unsigned& r0, unsigned& r1,
                                      unsigned& r2, unsigned& r3, unsigned addr) {
    asm volatile("ldmatrix.sync.aligned.m8n8.x4.shared.b16 {%0,%1,%2,%3}, [%4];"
                 : "=r"(r0), "=r"(r1), "=r"(r2), "=r"(r3) : "r"(addr));
}
__device__ __forceinline__ float silu_f(float x) {
    return x / (1.0f + __expf(-x));
}
__device__ __forceinline__ unsigned s2u(const void* p) {
    return (unsigned)__cvta_generic_to_shared(p);
}
#define CPA16(d, s) asm volatile("cp.async.ca.shared.global [%0], [%1], 16;" :: "r"(d), "l"(s))
#define CP_COMMIT() asm volatile("cp.async.commit_group;")
#define CP_WAIT(n)  asm volatile("cp.async.wait_group %0;" :: "n"(n))

// =================================================================
// prep
// =================================================================
__global__ void prep_k(const float* __restrict__ X, const float* __restrict__ WQ,
                       const float* __restrict__ WK, const float* __restrict__ WV,
                       const float* __restrict__ WG, const float* __restrict__ WO)
{
    int idx = blockIdx.x * 256 + threadIdx.x;
    const int XW = M_TOT * KW;
    if (idx < XW) {
        int row = idx >> 8, kw = idx & 255;
        const float* p = X + (size_t)row * KDIM + 2 * kw;
        g_Xh[idx] = packh2(p[0], p[1]);
        return;
    }
    int off = idx - XW;
    if (off < 5 * (WSZ / 2)) {
        int w = off >> 17, sub = off & (WSZ / 2 - 1);
        int n = sub >> 8, kw = sub & 255;
        int k0 = kw * 2;
        float v0, v1;
        if (w < 3) {
            const float* p = (w == 0) ? WQ : (w == 1) ? WK : WV;
            size_t hb = (size_t)(n >> 6) * (KDIM * DHEAD) + (n & 63);
            v0 = p[hb + (size_t)k0 * DHEAD];
            v1 = p[hb + (size_t)(k0 + 1) * DHEAD];
        } else {
            const float* p = (w == 3) ? WG : WO;
            v0 = p[(size_t)k0 * NDIM + n];
            v1 = p[(size_t)(k0 + 1) * NDIM + n];
        }
        g_Wh[off] = packh2(v0, v1);
        return;
    }
    int t = off - 5 * (WSZ / 2);
    if (t < S_LEN * 32) {
        int s = t >> 5, j = t & 31;
        double invf = pow(10000.0, -(double)j / 32.0);
        double ang = (double)s * invf;
        g_tsin[t] = (float)sin(ang);
        g_tcos[t] = (float)cos(ang);
        double sv = (2.0 * j + 0.4 * 64.0) / (1.4 * 64.0);
        g_tscl[t] = (float)pow(sv, (double)s / 512.0);
    }
}

// =================================================================
// fp16 GEMM, 128xBN tile, BK=32 halves, 256 thr, 3-stage cp.async,
// ldmatrix fragment loads. Stride 20 words. NT = 16-col tiles per warp.
// MODE 0 (BN=128): bz 0..2 -> Q/K/V (rotary; V transposed), bz 3 -> gate.
// MODE 2 (BN=64):  g_AGh @ WO^T -> fp32 out.
// =================================================================
#define NIT 16

template<int MODE, int BN>
__global__ void __launch_bounds__(256) gemm_h(float* __restrict__ Cout)
{
    constexpr int NT = BN / 32;          // 16-wide n-tiles per warp (warp owns BN/2 cols)
    extern __shared__ unsigned gsm[];
    unsigned (*As)[20] = (unsigned(*)[20])gsm;                    // [3*128][20]
    unsigned (*Bs)[20] = (unsigned(*)[20])(gsm + 3 * 128 * 20);   // [3*BN][20]
    const unsigned AsU = s2u(As), BsU = s2u(Bs);

    const int bz = (MODE == 0) ? blockIdx.z : 4;
    const unsigned* Ag = (MODE == 0) ? g_Xh : g_AGh;
    const unsigned* Bg = g_Wh + (size_t)bz * (WSZ / 2);

    const int bm = blockIdx.y * 128;
    const int bn = blockIdx.x * BN;
    const int tid = threadIdx.x;
    const int warp = tid >> 5, lane = tid & 31;
    const int grp = lane >> 2, tig = lane & 3;
    const int wm = (warp & 3) * 32, wn = (warp >> 2) * (BN / 2);

    // ldmatrix lane-address components
    const int aRow = (lane & 7) + ((lane >> 3) & 1) * 8;   // m row within 16
    const int aKof = ((lane >> 4) & 1) * 4;                // k word offset
    const int bRow = (lane & 7) + ((lane >> 4) & 1) * 8;   // n row within 16
    const int bKof = ((lane >> 3) & 1) * 4;

    float acc[2][NT * 2][4];
#pragma unroll
    for (int mt = 0; mt < 2; mt++)
#pragma unroll
        for (int nt = 0; nt < NT * 2; nt++)
#pragma unroll
            for (int i = 0; i < 4; i++) acc[mt][nt][i] = 0.0f;

    auto load_stage = [&](int s) {
        const int st = s % 3;
#pragma unroll
        for (int r = 0; r < 2; r++) {
            int c = tid + r * 256;
            int row = c >> 2, w4 = (c & 3) * 4;
            CPA16(s2u(&As[st * 128 + row][w4]),
                  &Ag[(size_t)(bm + row) * KW + s * 16 + w4]);
        }
#pragma unroll
        for (int r = 0; r < (BN == 128 ? 2 : 1); r++) {
            int c = tid + r * 256;
            int row = c >> 2, w4 = (c & 3) * 4;
            CPA16(s2u(&Bs[st * BN + row][w4]),
                  &Bg[(size_t)(bn + row) * KW + s * 16 + w4]);
        }
    };

    load_stage(0); CP_COMMIT();
    load_stage(1); CP_COMMIT();

    for (int it = 0; it < NIT; it++) {
        const int st = it % 3;
        if (it + 1 < NIT) { CP_WAIT(1); } else { CP_WAIT(0); }
        __syncthreads();
        if (it + 2 < NIT) { load_stage(it + 2); CP_COMMIT(); }

#pragma unroll
        for (int ks = 0; ks < 2; ks++) {
            int kw = ks * 8;
            unsigned aF[2][4];
#pragma unroll
            for (int mt = 0; mt < 2; mt++) {
                unsigned addr = AsU +
                    (((st * 128 + wm + mt * 16 + aRow) * 20) + kw + aKof) * 4;
                ldsm4(aF[mt][0], aF[mt][1], aF[mt][2], aF[mt][3], addr);
            }
#pragma unroll
            for (int p = 0; p < NT; p++) {
                unsigned b[4];
                unsigned addr = BsU +
                    (((st * BN + wn + p * 16 + bRow) * 20) + kw + bKof) * 4;
                ldsm4(b[0], b[1], b[2], b[3], addr);
                mma_f16(acc[0][2 * p],     aF[0], b);
                mma_f16(acc[1][2 * p],     aF[1], b);
                mma_f16(acc[0][2 * p + 1], aF[0], b + 2);
                mma_f16(acc[1][2 * p + 1], aF[1], b + 2);
            }
        }
    }

    // ---- epilogue ----
#pragma unroll
    for (int mt = 0; mt < 2; mt++) {
        int row0 = bm + wm + mt * 16 + grp;
#pragma unroll
        for (int nt = 0; nt < NT * 2; nt++) {
            int col = bn + wn + nt * 8 + tig * 2;
#pragma unroll
            for (int h = 0; h < 2; h++) {
                int row = row0 + h * 8;
                float c0 = acc[mt][nt][h * 2], c1 = acc[mt][nt][h * 2 + 1];
                if (MODE == 0) {
                    if (bz == 3) {
                        *(float2*)&g_Gate[(size_t)row * NDIM + col] =
                            make_float2(silu_f(c0), silu_f(c1));
                    } else {
                        int gH = col >> 6, d = col & 63;
                        int s = row & (S_LEN - 1), bnI = row >> 10;
                        float o0 = c0, o1 = c1;
                        if (bz < 2) {
                            int ti = (s << 5) + (d >> 1);
                            float sn = g_tsin[ti], cs = g_tcos[ti], sc = g_tscl[ti];
                            if (bz == 1) sc = 1.0f / sc;
                            o0 = (c0 * cs - c1 * sn) * sc;
                            o1 = (c1 * cs + c0 * sn) * sc;
                        }
                        int gb = gH * 8 + bnI;
                        if (bz == 2) {
                            __half* vp = (__half*)g_Vh;
                            vp[((size_t)gb * 64 + d) * S_LEN + s]     = __float2half_rn(o0);
                            vp[((size_t)gb * 64 + d + 1) * S_LEN + s] = __float2half_rn(o1);
                        } else {
                            unsigned* dst = (bz == 0) ? g_Qh : g_Kh;
                            dst[((size_t)gb * S_LEN + s) * 32 + (d >> 1)] = packh2(o0, o1);
                        }
                    }
                } else {
                    *(float2*)&Cout[(size_t)row * NDIM + col] = make_float2(c0, c1);
                }
            }
        }
    }
}
#define GEMM_SMEM0 ((3 * 128 * 20 + 3 * 128 * 20) * 4)
#define GEMM_SMEM2 ((3 * 128 * 20 + 3 * 64 * 20) * 4)

// =================================================================
// Retention fp16: register-resident S, hoisted Q fragments, ldmatrix
// K/V fragment loads. 256 thr (8 warps x 16 rows), K/V tile 64,
// 3-stage cp.async. Stride 36 words. Fused GroupNorm + gate.
// =================================================================
#define ATTN_SMEM ((512 * 36 + 64) * 4)

__global__ void __launch_bounds__(256) attn_h(const float* __restrict__ gnw,
                                              const float* __restrict__ gnb)
{
    extern __shared__ unsigned sm4[];
    unsigned (*Qs)[36]  = (unsigned(*)[36])sm4;                 // 128 x [d/2]
    unsigned (*Ks)[36]  = (unsigned(*)[36])(sm4 + 128 * 36);    // 3*64 x [d/2]
    unsigned (*VsT)[36] = (unsigned(*)[36])(sm4 + 320 * 36);    // 3*64 (d) x [key/2]
    const unsigned QsU = s2u(Qs), KsU = s2u(Ks), VsU = s2u(VsT);

    const int qt  = 7 - blockIdx.x;
    const int gbn = blockIdx.y;
    const int g  = gbn >> 3;
    const int bn = gbn & 7;
    const int qbase = qt * 128;

    const unsigned* Qp = g_Qh + (size_t)gbn * S_LEN * 32;
    const unsigned* Kp = g_Kh + (size_t)gbn * S_LEN * 32;
    const unsigned* Vp = g_Vh + (size_t)gbn * DHEAD * 512;

    const int tid = threadIdx.x;
    const int warp = tid >> 5, lane = tid & 31;
    const int grp = lane >> 2, tig = lane & 3;

    const int aRow = (lane & 7) + ((lane >> 3) & 1) * 8;
    const int aKof = ((lane >> 4) & 1) * 4;
    const int bRow = (lane & 7) + ((lane >> 4) & 1) * 8;
    const int bKof = ((lane >> 3) & 1) * 4;

    double tt = log(1.0 / 32.0) + (double)g * (log(1.0 / 512.0) - log(1.0 / 32.0)) / 7.0;
    const float lng = (float)log(1.0 - exp(tt));

    auto load_kv = [&](int kt, int st) {
        int kbase = kt * 64;
#pragma unroll
        for (int r = 0; r < 2; r++) {
            int c = tid + r * 256;
            int row = c >> 3, w4 = (c & 7) * 4;
            CPA16(s2u(&Ks[st * 64 + row][w4]), &Kp[(size_t)(kbase + row) * 32 + w4]);
        }
#pragma unroll
        for (int r = 0; r < 2; r++) {
            int c = tid + r * 256;
            int row = c >> 3, w4 = (c & 7) * 4;   // row = d
            CPA16(s2u(&VsT[st * 64 + row][w4]), &Vp[(size_t)row * 512 + (kbase >> 1) + w4]);
        }
    };

    const int nkt = 2 * qt + 2;

#pragma unroll
    for (int r = 0; r < 4; r++) {
        int c = tid + r * 256;
        int row = c >> 3, w4 = (c & 7) * 4;
        CPA16(s2u(&Qs[row][w4]), &Qp[(size_t)(qbase + row) * 32 + w4]);
    }
    load_kv(0, 0); CP_COMMIT();
    load_kv(1, 1); CP_COMMIT();

    // decay coefficients (registers, loop-invariant)
    float eq[2], cej0[8], cej1[8];
    eq[0] = __expf(lng * (float)(warp * 16 + grp));
    eq[1] = __expf(lng * (float)(warp * 16 + grp + 8));
#pragma unroll
    for (int nt = 0; nt < 8; nt++) {
        int jl = nt * 8 + tig * 2;
        cej0[nt] = __expf(lng * (float)(63 - jl));
        cej1[nt] = __expf(lng * (float)(62 - jl));
    }

    float yacc[8][4];
#pragma unroll
    for (int nt = 0; nt < 8; nt++)
#pragma unroll
        for (int i = 0; i < 4; i++) yacc[nt][i] = 0.0f;

    unsigned qF[4][4];
    const int rq = warp * 16;

    for (int kt = 0; kt < nkt; kt++) {
        const int st = kt % 3;
        const int kbase = kt * 64;
        if (kt + 1 < nkt) { CP_WAIT(1); } else { CP_WAIT(0); }
        __syncthreads();
        if (kt + 2 < nkt) { load_kv(kt + 2, (kt + 2) % 3); CP_COMMIT(); }

        if (kt == 0) {
#pragma unroll
            for (int ks = 0; ks < 4; ks++) {
                unsigned addr = QsU + (((rq + aRow) * 36) + ks * 8 + aKof) * 4;
                ldsm4(qF[ks][0], qF[ks][1], qF[ks][2], qF[ks][3], addr);
            }
        }

        // ---- mma1: scores = Q @ K^T ----
        float sacc[8][4];
#pragma unroll
        for (int nt = 0; nt < 8; nt++)
#pragma unroll
            for (int i = 0; i < 4; i++) sacc[nt][i] = 0.0f;

#pragma unroll
        for (int ks = 0; ks < 4; ks++) {
#pragma unroll
            for (int p = 0; p < 4; p++) {
                unsigned b[4];
                unsigned addr = KsU + (((st * 64 + p * 16 + bRow) * 36) + ks * 8 + bKof) * 4;
                ldsm4(b[0], b[1], b[2], b[3], addr);
                mma_f16(sacc[2 * p],     qF[ks], b);
                mma_f16(sacc[2 * p + 1], qF[ks], b + 2);
            }
        }

        // ---- decay + mask -> register S (mma2 A-fragments) ----
        const float tf = __expf(lng * (float)(qbase - kbase - 63));
        const float d0 = eq[0] * tf, d1 = eq[1] * tf;
        const bool edge = (kt >= nkt - 2);
        float mm[8][4];
#pragma unroll
        for (int nt = 0; nt < 8; nt++) {
            mm[nt][0] = sacc[nt][0] * d0 * cej0[nt];
            mm[nt][1] = sacc[nt][1] * d0 * cej1[nt];
            mm[nt][2] = sacc[nt][2] * d1 * cej0[nt];
            mm[nt][3] = sacc[nt][3] * d1 * cej1[nt];
            if (edge) {
                int kj = kbase + nt * 8 + tig * 2;
                int qi0 = qbase + rq + grp, qi1 = qi0 + 8;
                if (qi0 < kj)     mm[nt][0] = 0.0f;
                if (qi0 < kj + 1) mm[nt][1] = 0.0f;
                if (qi1 < kj)     mm[nt][2] = 0.0f;
                if (qi1 < kj + 1) mm[nt][3] = 0.0f;
            }
        }
        unsigned aS[4][4];
#pragma unroll
        for (int k2 = 0; k2 < 4; k2++) {
            aS[k2][0] = packh2(mm[2 * k2][0],     mm[2 * k2][1]);
            aS[k2][1] = packh2(mm[2 * k2][2],     mm[2 * k2][3]);
            aS[k2][2] = packh2(mm[2 * k2 + 1][0], mm[2 * k2 + 1][1]);
            aS[k2][3] = packh2(mm[2 * k2 + 1][2], mm[2 * k2 + 1][3]);
        }

        // ---- mma2: Y += S @ V^T-tile ----
#pragma unroll
        for (int k2 = 0; k2 < 4; k2++) {
#pragma unroll
            for (int p = 0; p < 4; p++) {
                unsigned b[4];
                unsigned addr = VsU + (((st * 64 + p * 16 + bRow) * 36) + k2 * 8 + bKof) * 4;
                ldsm4(b[0], b[1], b[2], b[3], addr);
                mma_f16(yacc[2 * p],     aS[k2], b);
                mma_f16(yacc[2 * p + 1], aS[k2], b + 2);
            }
        }
    }

    // ---- GroupNorm + gate + half2 store ----
#pragma unroll
    for (int h = 0; h < 2; h++) {
        int rl = rq + grp + h * 8;
        int qi = qbase + rl;
        float s = 0.0f, sq = 0.0f;
#pragma unroll
        for (int nt = 0; nt < 8; nt++) {
            float v0 = yacc[nt][h * 2], v1 = yacc[nt][h * 2 + 1];
            s += v0 + v1;
            sq += v0 * v0 + v1 * v1;
        }
        s  += __shfl_xor_sync(0xffffffffu, s, 1);
        s  += __shfl_xor_sync(0xffffffffu, s, 2);
        sq += __shfl_xor_sync(0xffffffffu, sq, 1);
        sq += __shfl_xor_sync(0xffffffffu, sq, 2);
        float mean = s * (1.0f / 64.0f);
        float var = sq * (1.0f / 64.0f) - mean * mean;
        float rstd = rsqrtf(var + 1e-5f);
        size_t fbase = ((size_t)bn * S_LEN + qi) * NDIM + g * 64;
#pragma unroll
        for (int nt = 0; nt < 8; nt++) {
            int col = nt * 8 + tig * 2;
            float w0 = gnw[g * 64 + col], w1 = gnw[g * 64 + col + 1];
            float b0 = gnb[g * 64 + col], b1 = gnb[g * 64 + col + 1];
            float2 gt = *(const float2*)&g_Gate[fbase + col];
            float o0 = ((yacc[nt][h * 2]     - mean) * rstd * w0 + b0) * gt.x;
            float o1 = ((yacc[nt][h * 2 + 1] - mean) * rstd * w1 + b1) * gt.y;
            g_AGh[(fbase + col) >> 1] = packh2(o0, o1);
        }
    }
}

// =================================================================
extern "C" void kernel_launch(void* const* d_in, const int* in_sizes, int n_in,
                              void* d_out, int out_size)
{
    const float* X   = (const float*)d_in[0];
    const float* WQ  = (const float*)d_in[1];
    const float* WK  = (const float*)d_in[2];
    const float* WV  = (const float*)d_in[3];
    const float* WG  = (const float*)d_in[4];
    const float* WO  = (const float*)d_in[5];
    const float* gnw = (const float*)d_in[6];
    const float* gnb = (const float*)d_in[7];
    float* out = (float*)d_out;

    cudaFuncSetAttribute((const void*)gemm_h<0, 128>,
                         cudaFuncAttributeMaxDynamicSharedMemorySize, GEMM_SMEM0);
    cudaFuncSetAttribute((const void*)gemm_h<2, 64>,
                         cudaFuncAttributeMaxDynamicSharedMemorySize, GEMM_SMEM2);
    cudaFuncSetAttribute((const void*)attn_h,
                         cudaFuncAttributeMaxDynamicSharedMemorySize, ATTN_SMEM);

    int prep_elems = M_TOT * KW + 5 * (WSZ / 2) + S_LEN * 32;
    prep_k<<<(prep_elems + 255) / 256, 256>>>(X, WQ, WK, WV, WG, WO);

    gemm_h<0, 128><<<dim3(NDIM / 128, M_TOT / 128, 4), 256, GEMM_SMEM0>>>(nullptr);
    attn_h<<<dim3(8, GBN), 256, ATTN_SMEM>>>(gnw, gnb);
    gemm_h<2, 64><<<dim3(NDIM / 64, M_TOT / 128, 1), 256, GEMM_SMEM2>>>(out);
}